// round 15
// baseline (speedup 1.0000x reference)
#include <cuda_runtime.h>

#define BB 64
#define TT 100
#define DD 32
#define LL 64
#define KK 16
#define HH 50
#define NT 512

typedef unsigned long long u64;

// ---------------- global scratch (no allocation allowed) ----------------
__device__ float g_w[BB * TT * KK];
__device__ float g_muf[BB * TT * LL];
__device__ float g_mup[BB * TT * LL];
__device__ float g_Sigf[(size_t)BB * TT * LL * LL];
__device__ float g_Sigp[(size_t)BB * TT * LL * LL];
__device__ float g_J[(size_t)BB * (TT - 1) * LL * LL];    // X = J^T per (t,b)
__device__ float g_B[(size_t)BB * (TT - 1) * LL * LL];    // B_t = Sf - J Sp J^T
__device__ float g_bv[(size_t)BB * (TT - 1) * LL];        // b_t = mf - J mp1
__device__ float g_cSig[BB * LL * LL];                    // fwd carry between parts
__device__ float g_cMu[BB * LL];

// ---------------- packed f32x2 helpers ----------------
__device__ __forceinline__ u64 splat2(float a) {
    u64 r; asm("mov.b64 %0, {%1,%1};" : "=l"(r) : "f"(a)); return r;
}
__device__ __forceinline__ u64 pk2(float x, float y) {
    u64 r; asm("mov.b64 %0, {%1,%2};" : "=l"(r) : "f"(x), "f"(y)); return r;
}
__device__ __forceinline__ float2 unpk(u64 v) {
    float2 r; asm("mov.b64 {%0,%1}, %2;" : "=f"(r.x), "=f"(r.y) : "l"(v)); return r;
}
__device__ __forceinline__ void vfma(u64& d, u64 a, u64 b) {
    asm("fma.rn.f32x2 %0, %1, %2, %0;" : "+l"(d) : "l"(a), "l"(b));
}

// ---- 8x4 register-tile matmul ----
template<int KN, int SA, int SB, bool NEG>
__device__ __forceinline__ void mm84(u64 acc[8][2], const float* __restrict__ aT,
                                     const float* __restrict__ bB) {
#pragma unroll 16
    for (int k = 0; k < KN; k++) {
        float4 a0 = *(const float4*)(aT + k * SA);
        float4 a1 = *(const float4*)(aT + k * SA + 4);
        ulonglong2 bv = *(const ulonglong2*)(bB + k * SB);
        u64 s;
        s = splat2(NEG ? -a0.x : a0.x); vfma(acc[0][0], s, bv.x); vfma(acc[0][1], s, bv.y);
        s = splat2(NEG ? -a0.y : a0.y); vfma(acc[1][0], s, bv.x); vfma(acc[1][1], s, bv.y);
        s = splat2(NEG ? -a0.z : a0.z); vfma(acc[2][0], s, bv.x); vfma(acc[2][1], s, bv.y);
        s = splat2(NEG ? -a0.w : a0.w); vfma(acc[3][0], s, bv.x); vfma(acc[3][1], s, bv.y);
        s = splat2(NEG ? -a1.x : a1.x); vfma(acc[4][0], s, bv.x); vfma(acc[4][1], s, bv.y);
        s = splat2(NEG ? -a1.y : a1.y); vfma(acc[5][0], s, bv.x); vfma(acc[5][1], s, bv.y);
        s = splat2(NEG ? -a1.z : a1.z); vfma(acc[6][0], s, bv.x); vfma(acc[6][1], s, bv.y);
        s = splat2(NEG ? -a1.w : a1.w); vfma(acc[7][0], s, bv.x); vfma(acc[7][1], s, bv.y);
    }
}

__device__ __forceinline__ void zero84(u64 acc[8][2]) {
#pragma unroll
    for (int r = 0; r < 8; r++) { acc[r][0] = 0ull; acc[r][1] = 0ull; }
}
template<int SS>
__device__ __forceinline__ void load84(u64 acc[8][2], const float* src) {
#pragma unroll
    for (int r = 0; r < 8; r++) {
        ulonglong2 w = *(const ulonglong2*)(src + r * SS);
        acc[r][0] = w.x; acc[r][1] = w.y;
    }
}
template<int SS>
__device__ __forceinline__ void store84(float* dst, const u64 acc[8][2]) {
#pragma unroll
    for (int r = 0; r < 8; r++)
        *(ulonglong2*)(dst + r * SS) = make_ulonglong2(acc[r][0], acc[r][1]);
}
template<int SD>
__device__ __forceinline__ void storeT84(float* dstT, const u64 acc[8][2]) {
    float va[8][4];
#pragma unroll
    for (int r = 0; r < 8; r++) {
        float2 e0 = unpk(acc[r][0]);
        float2 e1 = unpk(acc[r][1]);
        va[r][0] = e0.x; va[r][1] = e0.y; va[r][2] = e1.x; va[r][3] = e1.y;
    }
#pragma unroll
    for (int c = 0; c < 4; c++) {
        *(ulonglong2*)(dstT + c * SD) =
            make_ulonglong2(pk2(va[0][c], va[1][c]), pk2(va[2][c], va[3][c]));
        *(ulonglong2*)(dstT + c * SD + 4) =
            make_ulonglong2(pk2(va[4][c], va[5][c]), pk2(va[6][c], va[7][c]));
    }
}

// ---- 4x4 tile (for 32-row outputs) ----
template<int KN, int SA, int SB, bool NEG>
__device__ __forceinline__ void mm44(u64 acc[4][2], const float* __restrict__ aT,
                                     const float* __restrict__ bB) {
#pragma unroll 16
    for (int k = 0; k < KN; k++) {
        float4 a0 = *(const float4*)(aT + k * SA);
        ulonglong2 bv = *(const ulonglong2*)(bB + k * SB);
        u64 s;
        s = splat2(NEG ? -a0.x : a0.x); vfma(acc[0][0], s, bv.x); vfma(acc[0][1], s, bv.y);
        s = splat2(NEG ? -a0.y : a0.y); vfma(acc[1][0], s, bv.x); vfma(acc[1][1], s, bv.y);
        s = splat2(NEG ? -a0.z : a0.z); vfma(acc[2][0], s, bv.x); vfma(acc[2][1], s, bv.y);
        s = splat2(NEG ? -a0.w : a0.w); vfma(acc[3][0], s, bv.x); vfma(acc[3][1], s, bv.y);
    }
}
__device__ __forceinline__ void zero44(u64 acc[4][2]) {
#pragma unroll
    for (int r = 0; r < 4; r++) { acc[r][0] = 0ull; acc[r][1] = 0ull; }
}

// ---------------- kernel 1: mixing weights w = softmax(MLP(joint)) ----------------
__global__ void w_kernel(const float* __restrict__ obs, const float* __restrict__ start,
                         const float* __restrict__ W1, const float* __restrict__ b1,
                         const float* __restrict__ W2, const float* __restrict__ b2) {
    __shared__ float sj[DD];
    __shared__ float sh[HH];
    __shared__ float se[KK];
    int bt = blockIdx.x;
    int b = bt / TT, t = bt % TT;
    int tid = threadIdx.x;
    if (tid < DD) sj[tid] = (t == 0) ? start[tid] : obs[((size_t)b * TT + t - 1) * DD + tid];
    __syncthreads();
    if (tid < HH) {
        float a = b1[tid];
        for (int d = 0; d < DD; d++) a = fmaf(sj[d], W1[d * HH + tid], a);
        sh[tid] = fmaxf(a, 0.f);
    }
    __syncthreads();
    if (tid < KK) {
        float a = b2[tid];
        for (int j = 0; j < HH; j++) a = fmaf(sh[j], W2[j * KK + tid], a);
        se[tid] = a;
    }
    __syncthreads();
    if (tid == 0) {
        float m = se[0];
        for (int k = 1; k < KK; k++) m = fmaxf(m, se[k]);
        float ex[KK];
        float ssum = 0.f;
        for (int k = 0; k < KK; k++) { ex[k] = expf(se[k] - m); ssum += ex[k]; }
        float inv = 1.f / ssum;
        for (int k = 0; k < KK; k++) g_w[bt * KK + k] = ex[k] * inv;
    }
}

// ---------------- kernel 2: A_t / C_t mixing ----------------
__global__ void mix_kernel(const float* __restrict__ M, float* __restrict__ out, int ncols) {
    __shared__ float sM[KK * 512];
    __shared__ float sw[32 * KK];
    int tid = threadIdx.x;
    int ij0 = blockIdx.x * 512;
    int bt0 = blockIdx.y * 32;
    for (int idx = tid * 4; idx < KK * 512; idx += 256 * 4) {
        int k = idx / 512, c = idx % 512;
        *(float4*)&sM[idx] = *(const float4*)&M[(size_t)k * ncols + ij0 + c];
    }
    sw[tid]       = g_w[bt0 * KK + tid];
    sw[tid + 256] = g_w[bt0 * KK + tid + 256];
    __syncthreads();

    int btl = (tid >> 5) * 4;
    int jl  = (tid & 31) * 16;
    float acc[4][16];
#pragma unroll
    for (int u = 0; u < 4; u++)
#pragma unroll
        for (int v = 0; v < 16; v++) acc[u][v] = 0.f;

    for (int k = 0; k < KK; k++) {
        float w0 = sw[(btl + 0) * KK + k];
        float w1 = sw[(btl + 1) * KK + k];
        float w2 = sw[(btl + 2) * KK + k];
        float w3 = sw[(btl + 3) * KK + k];
        float m[16];
#pragma unroll
        for (int v = 0; v < 16; v += 4) *(float4*)&m[v] = *(float4*)&sM[k * 512 + jl + v];
#pragma unroll
        for (int v = 0; v < 16; v++) {
            acc[0][v] = fmaf(w0, m[v], acc[0][v]);
            acc[1][v] = fmaf(w1, m[v], acc[1][v]);
            acc[2][v] = fmaf(w2, m[v], acc[2][v]);
            acc[3][v] = fmaf(w3, m[v], acc[3][v]);
        }
    }
#pragma unroll
    for (int u = 0; u < 4; u++) {
        float* dst = &out[(size_t)(bt0 + btl + u) * ncols + ij0 + jl];
#pragma unroll
        for (int v = 0; v < 16; v += 4)
            *(float4*)&dst[v] = make_float4(acc[u][v], acc[u][v + 1], acc[u][v + 2], acc[u][v + 3]);
    }
}

// ---------------- forward Kalman filter: one CTA per batch, [t0, t1) ----------------
struct FwdS {
    float Sig[LL * LL];     // carry: predicted covariance (stride 64)
    float AtT[2][LL * 68];  // A transposed, double-buffered
    float CtT[2][LL * 36];  // C transposed, double-buffered
    float CS[DD * 68];      // CS0 = C@Sig (stride 68)
    float KgT[DD * 68];     // Kg^T (stride 68)
    float T2T[LL * 68];     // (A@Sigz)^T (stride 68)
    float Sigz[LL * LL];
    float Sst[DD * 34];     // S staging (stride 34)
    float P0[2][104];       // GJ raw pivot row p
    float P1[2][104];       // GJ raw pivot row p+1
    float F0[2][DD];        // GJ raw pivot column p
    float F1[2][DD];        // GJ raw pivot column p+1
    float Fd[DD];
    float mu[LL];
    float muz[LL];
    float r[DD];
    float y[2][DD];         // obs, double-buffered
};

extern __shared__ char smem_raw[];

__global__ __launch_bounds__(NT, 1) void fwd_kernel(const float* __restrict__ obs,
                                                    const float* __restrict__ outA,
                                                    const float* __restrict__ outC,
                                                    int t0, int t1) {
    FwdS& s = *(FwdS*)smem_raw;
    int tid = threadIdx.x;
    int b = blockIdx.x;
    if (t0 == 0) {
        for (int o = tid; o < LL * LL; o += NT) s.Sig[o] = ((o >> 6) == (o & 63)) ? 20.f : 0.f;
        if (tid < LL) s.mu[tid] = 0.f;
    } else {
        for (int o = tid * 4; o < LL * LL; o += NT * 4)
            *(float4*)&s.Sig[o] = *(const float4*)&g_cSig[b * 4096 + o];
        if (tid < LL) s.mu[tid] = g_cMu[b * LL + tid];
    }

    int it8 = (tid >> 4) * 8;        // i0
    int jt4 = (tid & 15) * 4;        // j0
    int ip4 = (tid >> 4) * 4;
    int sd = tid >> 4;               // 0..31
    int e0 = (tid & 15) * 2;         // 0..30
    int gr = tid / 12;
    int gq = tid - gr * 12;
    int gc = gq * 8;                 // 0..88 (cols 0..31 = S, 32..95 = RHS)
    bool gjA = (tid < 384);
    bool isRHS = gjA && (gc >= 32);
    int c0 = gc - 32;
    int pf = tid - 384;              // prefetch lane 0..127 (tid>=384)

    float v[8];                       // GJ register row-chunk

    // prologue: load A/C/y for t0 into buffer (t0&1)
    {
        int pb = t0 & 1;
        const float* Ag = outA + (size_t)(b * TT + t0) * (LL * LL);
        const float* Cg = outC + (size_t)(b * TT + t0) * (DD * LL);
        for (int o = tid * 4; o < LL * LL; o += NT * 4) {
            float4 w = *(const float4*)(Ag + o);
            int i = o >> 6, j = o & 63;
            s.AtT[pb][(j + 0) * 68 + i] = w.x;
            s.AtT[pb][(j + 1) * 68 + i] = w.y;
            s.AtT[pb][(j + 2) * 68 + i] = w.z;
            s.AtT[pb][(j + 3) * 68 + i] = w.w;
        }
        int o = tid * 4;
        if (o < DD * LL) {
            float4 w = *(const float4*)&Cg[o];
            int i = o >> 6, j = o & 63;
            s.CtT[pb][(j + 0) * 36 + i] = w.x;
            s.CtT[pb][(j + 1) * 36 + i] = w.y;
            s.CtT[pb][(j + 2) * 36 + i] = w.z;
            s.CtT[pb][(j + 3) * 36 + i] = w.w;
        }
        if (tid < DD) s.y[pb][tid] = obs[((size_t)b * TT + t0) * DD + tid];
    }
    __syncthreads();

    for (int t = t0; t < t1; t++) {
        int buf = t & 1;
        const float* At = s.AtT[buf];
        const float* Ct = s.CtT[buf];
        const float* Ag1 = outA + (size_t)(b * TT + t + 1) * (LL * LL);
        const float* Cg1 = outC + (size_t)(b * TT + t + 1) * (DD * LL);

        // p2: CS = C @ Sig (32x64) via 4x4 tiles on threads 0..127 ; r = y - C mu on 128..159
        if (tid < 128) {
            u64 acc[4][2];
            zero44(acc);
            mm44<LL, 36, LL, false>(acc, &Ct[ip4], &s.Sig[jt4]);
#pragma unroll
            for (int r2 = 0; r2 < 4; r2++)
                *(ulonglong2*)&s.CS[(ip4 + r2) * 68 + jt4] = make_ulonglong2(acc[r2][0], acc[r2][1]);
        } else if (tid < 160) {
            int m = tid - 128;
            float a = s.y[buf][m];
            for (int l = 0; l < LL; l++) a = fmaf(-Ct[l * 36 + m], s.mu[l], a);
            s.r[m] = a;
        }
        __syncthreads();

        // p3: S = CS0@C^T + 0.3 I
        {
            u64 sacc = pk2((sd == e0) ? 0.3f : 0.f, (sd == e0 + 1) ? 0.3f : 0.f);
            const float* crow = &s.CS[sd * 68];
#pragma unroll 8
            for (int k = 0; k < LL; k++)
                vfma(sacc, splat2(crow[k]), *(const u64*)&Ct[k * 36 + e0]);
            *(u64*)&s.Sst[sd * 34 + e0] = sacc;
        }
        __syncthreads();

        // p3b: GJ threads load register rows; initial publishes for pivot pair 0
        if (gjA) {
            if (gc < 32) {
#pragma unroll
                for (int i = 0; i < 8; i++) v[i] = s.Sst[gr * 34 + gc + i];
            } else {
#pragma unroll
                for (int i = 0; i < 8; i++) v[i] = s.CS[gr * 68 + c0 + i];
            }
            if (gr == 0) {
#pragma unroll
                for (int i = 0; i < 8; i++) s.P0[0][gc + i] = v[i];
            }
            if (gr == 1) {
#pragma unroll
                for (int i = 0; i < 8; i++) s.P1[0][gc + i] = v[i];
            }
            if (gq == 0) { s.F0[0][gr] = v[0]; s.F1[0][gr] = v[1]; }
        }
        __syncthreads();

        // Dual-pivot Gauss-Jordan (2 pivots/sync) with A/C prefetch on idle threads.
        for (int p = 0; p < DD; p += 2) {
            int par = (p >> 1) & 1;
            if (gjA) {
                float d0 = s.P0[par][p];
                float inv0 = __frcp_rn(d0);
                float f0p1 = s.P1[par][p] * inv0;
                float d1 = fmaf(-f0p1, s.P0[par][p + 1], s.P1[par][p + 1]);
                float inv1 = __frcp_rn(d1);
                float f0 = s.F0[par][gr] * inv0;
                float F1eff = (gr == p) ? s.F1[par][gr]
                                        : fmaf(-f0, s.P0[par][p + 1], s.F1[par][gr]);
                float f1 = F1eff * inv1;
                float a0 = (gr == p) ? 0.f : f0;
                float b1 = (gr == p + 1) ? 0.f : f1;
                float b0 = fmaf(-b1, f0p1, a0);
                float4 q0 = *(float4*)&s.P0[par][gc];
                float4 q1 = *(float4*)&s.P0[par][gc + 4];
                float4 r0 = *(float4*)&s.P1[par][gc];
                float4 r1 = *(float4*)&s.P1[par][gc + 4];
                v[0] = fmaf(-b0, q0.x, fmaf(-b1, r0.x, v[0]));
                v[1] = fmaf(-b0, q0.y, fmaf(-b1, r0.y, v[1]));
                v[2] = fmaf(-b0, q0.z, fmaf(-b1, r0.z, v[2]));
                v[3] = fmaf(-b0, q0.w, fmaf(-b1, r0.w, v[3]));
                v[4] = fmaf(-b0, q1.x, fmaf(-b1, r1.x, v[4]));
                v[5] = fmaf(-b0, q1.y, fmaf(-b1, r1.y, v[5]));
                v[6] = fmaf(-b0, q1.z, fmaf(-b1, r1.z, v[6]));
                v[7] = fmaf(-b0, q1.w, fmaf(-b1, r1.w, v[7]));
                int np = p + 2;
                if (np < DD) {
                    if (gr == np) {
#pragma unroll
                        for (int i = 0; i < 8; i++) s.P0[par ^ 1][gc + i] = v[i];
                    }
                    if (gr == np + 1) {
#pragma unroll
                        for (int i = 0; i < 8; i++) s.P1[par ^ 1][gc + i] = v[i];
                    }
                    if (np >= gc && np < gc + 8) {
                        s.F0[par ^ 1][gr] = v[np - gc];
                        s.F1[par ^ 1][gr] = v[np - gc + 1];
                    }
                } else {
#pragma unroll
                    for (int i = 0; i < 8; i++)
                        if (gr == gc + i) s.Fd[gr] = v[i];
                }
            } else if (t + 1 < TT) {
                // prefetch next step's A/C/y into buf^1 (threads 384..511)
                int itr = p >> 1;              // 0..15
                if (itr < 12) {
                    int idx = itr * 128 + pf;  // 0..1535
                    if (idx < 1024) {
                        int o = idx * 4;
                        float4 w = *(const float4*)(Ag1 + o);
                        int i = o >> 6, j = o & 63;
                        s.AtT[buf ^ 1][(j + 0) * 68 + i] = w.x;
                        s.AtT[buf ^ 1][(j + 1) * 68 + i] = w.y;
                        s.AtT[buf ^ 1][(j + 2) * 68 + i] = w.z;
                        s.AtT[buf ^ 1][(j + 3) * 68 + i] = w.w;
                    } else {
                        int o = (idx - 1024) * 4;
                        float4 w = *(const float4*)(Cg1 + o);
                        int i = o >> 6, j = o & 63;
                        s.CtT[buf ^ 1][(j + 0) * 36 + i] = w.x;
                        s.CtT[buf ^ 1][(j + 1) * 36 + i] = w.y;
                        s.CtT[buf ^ 1][(j + 2) * 36 + i] = w.z;
                        s.CtT[buf ^ 1][(j + 3) * 36 + i] = w.w;
                    }
                } else if (itr == 12 && pf < DD) {
                    s.y[buf ^ 1][pf] = obs[((size_t)b * TT + t + 1) * DD + pf];
                }
            }
            __syncthreads();
        }

        // writeout: KgT[m][i] = RHS[m][i] / diag[m]
        if (isRHS) {
            float dinv = __frcp_rn(s.Fd[gr]);
#pragma unroll
            for (int i = 0; i < 8; i += 2)
                *(u64*)&s.KgT[gr * 68 + c0 + i] = pk2(v[i] * dinv, v[i + 1] * dinv);
        }
        __syncthreads();

        // p6: Sigz = Sig - Kg@CS0 ; muz = mu + Kg r
        if (tid < 128) {
            u64 acc[8][2];
            load84<LL>(acc, &s.Sig[it8 * LL + jt4]);
            mm84<DD, 68, 68, true>(acc, &s.KgT[it8], &s.CS[jt4]);
            store84<LL>(&s.Sigz[it8 * LL + jt4], acc);
        } else if (tid < 192) {
            int i = tid - 128;
            float a = s.mu[i];
            for (int m = 0; m < DD; m++) a = fmaf(s.KgT[m * 68 + i], s.r[m], a);
            s.muz[i] = a;
        }
        __syncthreads();

        // p7: T2 = A @ Sigz stored transposed ; others store gmem outputs
        {
            size_t gb = (size_t)t * BB + b;
            if (tid < 128) {
                u64 acc[8][2];
                zero84(acc);
                mm84<LL, 68, LL, false>(acc, &At[it8], &s.Sigz[jt4]);
                storeT84<68>(&s.T2T[jt4 * 68 + it8], acc);
            } else {
                if (tid < 192) {
                    int i = tid - 128;
                    g_muf[gb * LL + i] = s.muz[i];
                    g_mup[gb * LL + i] = s.mu[i];
                }
                for (int o = 512 + (tid - 128) * 4; o < LL * LL; o += 384 * 4) {
                    *(float4*)&g_Sigf[gb * 4096 + o] = *(float4*)&s.Sigz[o];
                    *(float4*)&g_Sigp[gb * 4096 + o] = *(float4*)&s.Sig[o];
                }
                for (int o = (tid - 128) * 4; o < 512; o += 384 * 4) {
                    *(float4*)&g_Sigf[gb * 4096 + o] = *(float4*)&s.Sigz[o];
                    *(float4*)&g_Sigp[gb * 4096 + o] = *(float4*)&s.Sig[o];
                }
            }
        }
        __syncthreads();

        // p8: Sig_new = T2 @ A^T + 0.8 I ; mu_new = A muz
        if (tid < 128) {
            u64 acc[8][2];
#pragma unroll
            for (int r2 = 0; r2 < 8; r2++) {
                int i = it8 + r2;
                acc[r2][0] = pk2((i == jt4) ? 0.8f : 0.f, (i == jt4 + 1) ? 0.8f : 0.f);
                acc[r2][1] = pk2((i == jt4 + 2) ? 0.8f : 0.f, (i == jt4 + 3) ? 0.8f : 0.f);
            }
            mm84<LL, 68, 68, false>(acc, &s.T2T[it8], &At[jt4]);
            store84<LL>(&s.Sig[it8 * LL + jt4], acc);
        } else if (tid < 192) {
            int i = tid - 128;
            float a = 0.f;
            for (int k = 0; k < LL; k++) a = fmaf(At[k * 68 + i], s.muz[k], a);
            s.mu[i] = a;
        }
        __syncthreads();
    }

    // epilogue: persist carry for next part
    if (t1 < TT) {
        for (int o = tid * 4; o < LL * LL; o += NT * 4)
            *(float4*)&g_cSig[b * 4096 + o] = *(float4*)&s.Sig[o];
        if (tid < LL) g_cMu[b * LL + tid] = s.mu[tid];
    }
}

// ---------------- J precompute: fully parallel over (b, t) ----------------
struct JkS {
    float sAT[LL * 68];     // A_{t+1} transposed; after GJ reused as X = J^T rows
    float sSf[LL * LL];
    float sRHS[LL * 68];    // RHS = A @ Sf (rows, stride 68)
    float Prow[2][144];
    float Fcol[2][LL];
    float Fd[LL];
    float smf[LL];
    float smp[LL];
};

__global__ __launch_bounds__(NT, 2) void jk_kernel(const float* __restrict__ outA, int toff) {
    JkS& s = *(JkS*)smem_raw;
    int tid = threadIdx.x;
    int b = blockIdx.x;
    int t = blockIdx.y + toff;              // 0..T-2
    size_t gf = (size_t)t * BB + b;
    size_t gp = (size_t)(t + 1) * BB + b;

    int it8 = (tid >> 4) * 8;
    int jt4 = (tid & 15) * 4;

    int gr = tid >> 3;                      // 0..63
    int gq = tid & 7;
    int gc = gq * 16;                       // 0..112 (cols 0..63 = Sp, 64..127 = RHS)
    bool isRHS = (gc >= 64);
    int c0 = gc - 64;

    const float* Ag = outA + ((size_t)b * TT + (t + 1)) * (LL * LL);
    for (int o = tid * 4; o < LL * LL; o += NT * 4) {
        float4 w = *(const float4*)(Ag + o);
        int i = o >> 6, j = o & 63;
        s.sAT[(j + 0) * 68 + i] = w.x;
        s.sAT[(j + 1) * 68 + i] = w.y;
        s.sAT[(j + 2) * 68 + i] = w.z;
        s.sAT[(j + 3) * 68 + i] = w.w;
        *(float4*)&s.sSf[o] = *(const float4*)&g_Sigf[gf * 4096 + o];
    }
    if (tid < LL) s.smf[tid] = g_muf[gf * LL + tid];
    else if (tid < 2 * LL) s.smp[tid - LL] = g_mup[gp * LL + (tid - LL)];
    __syncthreads();

    // RHS = A @ Sf via 8x4 tiles (threads 0..127)
    if (tid < 128) {
        u64 acc[8][2];
        zero84(acc);
        mm84<LL, 68, LL, false>(acc, &s.sAT[it8], &s.sSf[jt4]);
        store84<68>(&s.sRHS[it8 * 68 + jt4], acc);
    }
    __syncthreads();

    float v[16];
    if (isRHS) {
#pragma unroll
        for (int i = 0; i < 16; i += 4) *(float4*)&v[i] = *(const float4*)&s.sRHS[gr * 68 + c0 + i];
    } else {
        const float* sp = &g_Sigp[gp * 4096 + gr * LL + gc];
#pragma unroll
        for (int i = 0; i < 16; i += 4) *(float4*)&v[i] = *(const float4*)&sp[i];
    }
    if (gr == 0) {
#pragma unroll
        for (int i = 0; i < 16; i++) s.Prow[0][gc + i] = v[i];
    }
    if (gq == 0) s.Fcol[0][gr] = v[0];
    __syncthreads();

    for (int p = 0; p < LL; p++) {
        int par = p & 1;
        float inv = __frcp_rn(s.Fcol[par][p]);
        float f = s.Fcol[par][gr] * inv;
        float4 p0 = *(float4*)&s.Prow[par][gc];
        float4 p1 = *(float4*)&s.Prow[par][gc + 4];
        float4 p2 = *(float4*)&s.Prow[par][gc + 8];
        float4 p3 = *(float4*)&s.Prow[par][gc + 12];
        if (gr != p) {
            v[0] = fmaf(-f, p0.x, v[0]);  v[1] = fmaf(-f, p0.y, v[1]);
            v[2] = fmaf(-f, p0.z, v[2]);  v[3] = fmaf(-f, p0.w, v[3]);
            v[4] = fmaf(-f, p1.x, v[4]);  v[5] = fmaf(-f, p1.y, v[5]);
            v[6] = fmaf(-f, p1.z, v[6]);  v[7] = fmaf(-f, p1.w, v[7]);
            v[8] = fmaf(-f, p2.x, v[8]);  v[9] = fmaf(-f, p2.y, v[9]);
            v[10] = fmaf(-f, p2.z, v[10]); v[11] = fmaf(-f, p2.w, v[11]);
            v[12] = fmaf(-f, p3.x, v[12]); v[13] = fmaf(-f, p3.y, v[13]);
            v[14] = fmaf(-f, p3.z, v[14]); v[15] = fmaf(-f, p3.w, v[15]);
        }
        int np = p + 1;
        if (np < LL) {
            if (gr == np) {
#pragma unroll
                for (int i = 0; i < 16; i++) s.Prow[par ^ 1][gc + i] = v[i];
            }
#pragma unroll
            for (int i = 0; i < 16; i++)
                if (np == gc + i) s.Fcol[par ^ 1][gr] = v[i];
        } else {
#pragma unroll
            for (int i = 0; i < 16; i++)
                if (gr == gc + i) s.Fd[gr] = v[i];
        }
        __syncthreads();
    }

    // X = J^T rows: write to g_J and into sAT (reused; A dead)
    if (isRHS) {
        float dinv = __frcp_rn(s.Fd[gr]);
        float* dst = &g_J[gf * 4096 + gr * LL + c0];
#pragma unroll
        for (int i = 0; i < 16; i += 4) {
            float4 w = make_float4(v[i] * dinv, v[i + 1] * dinv, v[i + 2] * dinv, v[i + 3] * dinv);
            *(float4*)&dst[i] = w;
            *(float4*)&s.sAT[gr * 68 + c0 + i] = w;
        }
    }
    __syncthreads();

    // B_t = Sf - RHS^T @ X (8x4 tiles) ; b_t = mf - J mp1
    if (tid < 128) {
        u64 acc[8][2];
        load84<LL>(acc, &s.sSf[it8 * LL + jt4]);
        mm84<LL, 68, 68, true>(acc, &s.sRHS[it8], &s.sAT[jt4]);
        store84<LL>(&g_B[gf * 4096 + it8 * LL + jt4], acc);
    } else if (tid < 192) {
        int i = tid - 128;
        float a = s.smf[i];
        for (int m = 0; m < LL; m++) a = fmaf(-s.sAT[m * 68 + i], s.smp[m], a);
        g_bv[gf * LL + i] = a;
    }
}

// ---------------- backward RTS recursion with smem prefetch ----------------
struct BwdS {
    float Sigs[LL * LL];    // carry: smoothed cov at t+1 (stride 64)
    float sX[2][LL * LL];   // X = J^T rows, double buffered
    float sB[LL * LL];      // B_t prefetch
    float T1T[LL * 68];     // (J@Sigs)^T
    float mus[LL];
    float musN[LL];
    float bv[2][LL];
};

__global__ __launch_bounds__(NT, 1) void bwd_kernel(float* __restrict__ outMu,
                                                    float* __restrict__ outSig) {
    BwdS& s = *(BwdS*)smem_raw;
    int tid = threadIdx.x;
    int b = blockIdx.x;
    int it8 = (tid >> 4) * 8;
    int jt4 = (tid & 15) * 4;

    {
        size_t gb = (size_t)(TT - 1) * BB + b;
        size_t g0 = (size_t)(TT - 2) * BB + b;
        for (int o = tid * 4; o < LL * LL; o += NT * 4) {
            float4 w = *(const float4*)&g_Sigf[gb * 4096 + o];
            *(float4*)&s.Sigs[o] = w;
            *(float4*)&outSig[gb * 4096 + o] = w;
            *(float4*)&s.sX[0][o] = *(const float4*)&g_J[g0 * 4096 + o];
        }
        if (tid < LL) {
            float w = g_muf[gb * LL + tid];
            s.mus[tid] = w;
            outMu[gb * LL + tid] = w;
            s.bv[0][tid] = g_bv[g0 * LL + tid];
        }
    }
    __syncthreads();

    for (int t = TT - 2; t >= 0; t--) {
        int cur = (TT - 2 - t) & 1;
        size_t gf = (size_t)t * BB + b;

        // m1: T1 = J @ Sigs (0..127) ; mu_s (128..191) ; prefetch B_t (192..447)
        if (tid < 128) {
            u64 acc[8][2];
            zero84(acc);
            mm84<LL, LL, LL, false>(acc, &s.sX[cur][it8], &s.Sigs[jt4]);
            storeT84<68>(&s.T1T[jt4 * 68 + it8], acc);
        } else if (tid < 192) {
            int i = tid - 128;
            float a = s.bv[cur][i];
            for (int k = 0; k < LL; k++) a = fmaf(s.sX[cur][k * LL + i], s.mus[k], a);
            s.musN[i] = a;
            outMu[gf * LL + i] = a;
        } else if (tid < 448) {
            for (int o = (tid - 192) * 4; o < LL * LL; o += 256 * 4)
                *(float4*)&s.sB[o] = *(const float4*)&g_B[gf * 4096 + o];
        }
        __syncthreads();

        // m2: Sigs_new = B + T1 @ X (0..127) ; mus copy (128..191) ; prefetch J/bv t-1 (192..511)
        if (tid < 128) {
            u64 acc[8][2];
            load84<LL>(acc, &s.sB[it8 * LL + jt4]);
            mm84<LL, 68, LL, false>(acc, &s.T1T[it8], &s.sX[cur][jt4]);
            store84<LL>(&s.Sigs[it8 * LL + jt4], acc);
            store84<LL>(&outSig[gf * 4096 + it8 * LL + jt4], acc);
        } else if (tid < 192) {
            s.mus[tid - 128] = s.musN[tid - 128];
        } else if (t > 0) {
            size_t gn = (size_t)(t - 1) * BB + b;
            if (tid < 448) {
                for (int o = (tid - 192) * 4; o < LL * LL; o += 256 * 4)
                    *(float4*)&s.sX[cur ^ 1][o] = *(const float4*)&g_J[gn * 4096 + o];
            } else {
                s.bv[cur ^ 1][tid - 448] = g_bv[gn * LL + (tid - 448)];
            }
        }
        __syncthreads();
    }
}

// ---------------- streams/events for graph-captured fork-join (created at load) ----------------
static cudaStream_t g_s1, g_s2;
static cudaEvent_t g_e0, g_e1, g_e2, g_e3;
namespace {
struct StreamInit {
    StreamInit() {
        cudaStreamCreateWithFlags(&g_s1, cudaStreamNonBlocking);
        cudaStreamCreateWithFlags(&g_s2, cudaStreamNonBlocking);
        cudaEventCreateWithFlags(&g_e0, cudaEventDisableTiming);
        cudaEventCreateWithFlags(&g_e1, cudaEventDisableTiming);
        cudaEventCreateWithFlags(&g_e2, cudaEventDisableTiming);
        cudaEventCreateWithFlags(&g_e3, cudaEventDisableTiming);
    }
};
StreamInit g_si;
}

// ---------------- launch ----------------
extern "C" void kernel_launch(void* const* d_in, const int* in_sizes, int n_in,
                              void* d_out, int out_size) {
    const float* obs   = (const float*)d_in[0];
    const float* start = (const float*)d_in[1];
    const float* W1    = (const float*)d_in[2];
    const float* b1    = (const float*)d_in[3];
    const float* W2    = (const float*)d_in[4];
    const float* b2    = (const float*)d_in[5];
    const float* A     = (const float*)d_in[6];
    const float* C     = (const float*)d_in[7];

    float* out = (float*)d_out;
    float* outMu  = out;                                   // (T,B,L)      409600
    float* outSig = out + 409600;                          // (T,B,L,L)  26214400
    float* outA   = out + 26624000;                        // (B,T,L,L)  26214400
    float* outC   = out + 52838400;                        // (B,T,D,L)  13107200

    cudaFuncSetAttribute(fwd_kernel, cudaFuncAttributeMaxDynamicSharedMemorySize, (int)sizeof(FwdS));
    cudaFuncSetAttribute(jk_kernel, cudaFuncAttributeMaxDynamicSharedMemorySize, (int)sizeof(JkS));
    cudaFuncSetAttribute(bwd_kernel, cudaFuncAttributeMaxDynamicSharedMemorySize, (int)sizeof(BwdS));

    // bridge: capture stream (legacy 0) -> g_s1
    cudaEventRecord(g_e0, 0);
    cudaStreamWaitEvent(g_s1, g_e0, 0);

    w_kernel<<<BB * TT, 64, 0, g_s1>>>(obs, start, W1, b1, W2, b2);

    dim3 gA(4096 / 512, BB * TT / 32);
    mix_kernel<<<gA, 256, 0, g_s1>>>(A, outA, 4096);
    dim3 gC(2048 / 512, BB * TT / 32);
    mix_kernel<<<gC, 256, 0, g_s1>>>(C, outC, 2048);

    // fwd part 1: t in [0, 50)
    fwd_kernel<<<BB, NT, sizeof(FwdS), g_s1>>>(obs, outA, outC, 0, 50);

    // fork: jk part 1 (t = 0..48) on g_s2, concurrent with fwd part 2 on g_s1
    cudaEventRecord(g_e1, g_s1);
    cudaStreamWaitEvent(g_s2, g_e1, 0);
    dim3 gJ1(BB, 49);
    jk_kernel<<<gJ1, NT, sizeof(JkS), g_s2>>>(outA, 0);

    // fwd part 2: t in [50, 100)
    fwd_kernel<<<BB, NT, sizeof(FwdS), g_s1>>>(obs, outA, outC, 50, TT);

    // jk part 2 (t = 49..98) on g_s1 after fwd completes
    dim3 gJ2(BB, 50);
    jk_kernel<<<gJ2, NT, sizeof(JkS), g_s1>>>(outA, 49);

    // join g_s2 into g_s1 before backward recursion
    cudaEventRecord(g_e2, g_s2);
    cudaStreamWaitEvent(g_s1, g_e2, 0);

    bwd_kernel<<<BB, NT, sizeof(BwdS), g_s1>>>(outMu, outSig);

    // bridge back: g_s1 -> capture stream (legacy 0)
    cudaEventRecord(g_e3, g_s1);
    cudaStreamWaitEvent(0, g_e3, 0);
}

// round 16
// speedup vs baseline: 1.0190x; 1.0190x over previous
#include <cuda_runtime.h>

#define BB 64
#define TT 100
#define DD 32
#define LL 64
#define KK 16
#define HH 50
#define NT 512

typedef unsigned long long u64;

// ---------------- global scratch (no allocation allowed) ----------------
__device__ float g_w[BB * TT * KK];
__device__ float g_muf[BB * TT * LL];
__device__ float g_mup[BB * TT * LL];
__device__ float g_Sigf[(size_t)BB * TT * LL * LL];
__device__ float g_Sigp[(size_t)BB * TT * LL * LL];
__device__ float g_J[(size_t)BB * (TT - 1) * LL * LL];    // X = J^T per (t,b)
__device__ float g_B[(size_t)BB * (TT - 1) * LL * LL];    // B_t = Sf - J Sp J^T
__device__ float g_bv[(size_t)BB * (TT - 1) * LL];        // b_t = mf - J mp1

// ---------------- packed f32x2 helpers ----------------
__device__ __forceinline__ u64 splat2(float a) {
    u64 r; asm("mov.b64 %0, {%1,%1};" : "=l"(r) : "f"(a)); return r;
}
__device__ __forceinline__ u64 pk2(float x, float y) {
    u64 r; asm("mov.b64 %0, {%1,%2};" : "=l"(r) : "f"(x), "f"(y)); return r;
}
__device__ __forceinline__ float2 unpk(u64 v) {
    float2 r; asm("mov.b64 {%0,%1}, %2;" : "=f"(r.x), "=f"(r.y) : "l"(v)); return r;
}
__device__ __forceinline__ void vfma(u64& d, u64 a, u64 b) {
    asm("fma.rn.f32x2 %0, %1, %2, %0;" : "+l"(d) : "l"(a), "l"(b));
}

// ---- 8x4 register-tile matmul ----
template<int KN, int SA, int SB, bool NEG>
__device__ __forceinline__ void mm84(u64 acc[8][2], const float* __restrict__ aT,
                                     const float* __restrict__ bB) {
#pragma unroll 16
    for (int k = 0; k < KN; k++) {
        float4 a0 = *(const float4*)(aT + k * SA);
        float4 a1 = *(const float4*)(aT + k * SA + 4);
        ulonglong2 bv = *(const ulonglong2*)(bB + k * SB);
        u64 s;
        s = splat2(NEG ? -a0.x : a0.x); vfma(acc[0][0], s, bv.x); vfma(acc[0][1], s, bv.y);
        s = splat2(NEG ? -a0.y : a0.y); vfma(acc[1][0], s, bv.x); vfma(acc[1][1], s, bv.y);
        s = splat2(NEG ? -a0.z : a0.z); vfma(acc[2][0], s, bv.x); vfma(acc[2][1], s, bv.y);
        s = splat2(NEG ? -a0.w : a0.w); vfma(acc[3][0], s, bv.x); vfma(acc[3][1], s, bv.y);
        s = splat2(NEG ? -a1.x : a1.x); vfma(acc[4][0], s, bv.x); vfma(acc[4][1], s, bv.y);
        s = splat2(NEG ? -a1.y : a1.y); vfma(acc[5][0], s, bv.x); vfma(acc[5][1], s, bv.y);
        s = splat2(NEG ? -a1.z : a1.z); vfma(acc[6][0], s, bv.x); vfma(acc[6][1], s, bv.y);
        s = splat2(NEG ? -a1.w : a1.w); vfma(acc[7][0], s, bv.x); vfma(acc[7][1], s, bv.y);
    }
}

__device__ __forceinline__ void zero84(u64 acc[8][2]) {
#pragma unroll
    for (int r = 0; r < 8; r++) { acc[r][0] = 0ull; acc[r][1] = 0ull; }
}
template<int SS>
__device__ __forceinline__ void load84(u64 acc[8][2], const float* src) {
#pragma unroll
    for (int r = 0; r < 8; r++) {
        ulonglong2 w = *(const ulonglong2*)(src + r * SS);
        acc[r][0] = w.x; acc[r][1] = w.y;
    }
}
template<int SS>
__device__ __forceinline__ void store84(float* dst, const u64 acc[8][2]) {
#pragma unroll
    for (int r = 0; r < 8; r++)
        *(ulonglong2*)(dst + r * SS) = make_ulonglong2(acc[r][0], acc[r][1]);
}
template<int SD>
__device__ __forceinline__ void storeT84(float* dstT, const u64 acc[8][2]) {
    float va[8][4];
#pragma unroll
    for (int r = 0; r < 8; r++) {
        float2 e0 = unpk(acc[r][0]);
        float2 e1 = unpk(acc[r][1]);
        va[r][0] = e0.x; va[r][1] = e0.y; va[r][2] = e1.x; va[r][3] = e1.y;
    }
#pragma unroll
    for (int c = 0; c < 4; c++) {
        *(ulonglong2*)(dstT + c * SD) =
            make_ulonglong2(pk2(va[0][c], va[1][c]), pk2(va[2][c], va[3][c]));
        *(ulonglong2*)(dstT + c * SD + 4) =
            make_ulonglong2(pk2(va[4][c], va[5][c]), pk2(va[6][c], va[7][c]));
    }
}

// ---- 4x4 tile (for 32-row outputs) ----
template<int KN, int SA, int SB, bool NEG>
__device__ __forceinline__ void mm44(u64 acc[4][2], const float* __restrict__ aT,
                                     const float* __restrict__ bB) {
#pragma unroll 16
    for (int k = 0; k < KN; k++) {
        float4 a0 = *(const float4*)(aT + k * SA);
        ulonglong2 bv = *(const ulonglong2*)(bB + k * SB);
        u64 s;
        s = splat2(NEG ? -a0.x : a0.x); vfma(acc[0][0], s, bv.x); vfma(acc[0][1], s, bv.y);
        s = splat2(NEG ? -a0.y : a0.y); vfma(acc[1][0], s, bv.x); vfma(acc[1][1], s, bv.y);
        s = splat2(NEG ? -a0.z : a0.z); vfma(acc[2][0], s, bv.x); vfma(acc[2][1], s, bv.y);
        s = splat2(NEG ? -a0.w : a0.w); vfma(acc[3][0], s, bv.x); vfma(acc[3][1], s, bv.y);
    }
}
__device__ __forceinline__ void zero44(u64 acc[4][2]) {
#pragma unroll
    for (int r = 0; r < 4; r++) { acc[r][0] = 0ull; acc[r][1] = 0ull; }
}

// ---------------- kernel 1: mixing weights w = softmax(MLP(joint)) ----------------
__global__ void w_kernel(const float* __restrict__ obs, const float* __restrict__ start,
                         const float* __restrict__ W1, const float* __restrict__ b1,
                         const float* __restrict__ W2, const float* __restrict__ b2) {
    __shared__ float sj[DD];
    __shared__ float sh[HH];
    __shared__ float se[KK];
    int bt = blockIdx.x;
    int b = bt / TT, t = bt % TT;
    int tid = threadIdx.x;
    if (tid < DD) sj[tid] = (t == 0) ? start[tid] : obs[((size_t)b * TT + t - 1) * DD + tid];
    __syncthreads();
    if (tid < HH) {
        float a = b1[tid];
        for (int d = 0; d < DD; d++) a = fmaf(sj[d], W1[d * HH + tid], a);
        sh[tid] = fmaxf(a, 0.f);
    }
    __syncthreads();
    if (tid < KK) {
        float a = b2[tid];
        for (int j = 0; j < HH; j++) a = fmaf(sh[j], W2[j * KK + tid], a);
        se[tid] = a;
    }
    __syncthreads();
    if (tid == 0) {
        float m = se[0];
        for (int k = 1; k < KK; k++) m = fmaxf(m, se[k]);
        float ex[KK];
        float ssum = 0.f;
        for (int k = 0; k < KK; k++) { ex[k] = expf(se[k] - m); ssum += ex[k]; }
        float inv = 1.f / ssum;
        for (int k = 0; k < KK; k++) g_w[bt * KK + k] = ex[k] * inv;
    }
}

// ---------------- kernel 2: A_t / C_t mixing ----------------
__global__ void mix_kernel(const float* __restrict__ M, float* __restrict__ out, int ncols) {
    __shared__ float sM[KK * 512];
    __shared__ float sw[32 * KK];
    int tid = threadIdx.x;
    int ij0 = blockIdx.x * 512;
    int bt0 = blockIdx.y * 32;
    for (int idx = tid * 4; idx < KK * 512; idx += 256 * 4) {
        int k = idx / 512, c = idx % 512;
        *(float4*)&sM[idx] = *(const float4*)&M[(size_t)k * ncols + ij0 + c];
    }
    sw[tid]       = g_w[bt0 * KK + tid];
    sw[tid + 256] = g_w[bt0 * KK + tid + 256];
    __syncthreads();

    int btl = (tid >> 5) * 4;
    int jl  = (tid & 31) * 16;
    float acc[4][16];
#pragma unroll
    for (int u = 0; u < 4; u++)
#pragma unroll
        for (int v = 0; v < 16; v++) acc[u][v] = 0.f;

    for (int k = 0; k < KK; k++) {
        float w0 = sw[(btl + 0) * KK + k];
        float w1 = sw[(btl + 1) * KK + k];
        float w2 = sw[(btl + 2) * KK + k];
        float w3 = sw[(btl + 3) * KK + k];
        float m[16];
#pragma unroll
        for (int v = 0; v < 16; v += 4) *(float4*)&m[v] = *(float4*)&sM[k * 512 + jl + v];
#pragma unroll
        for (int v = 0; v < 16; v++) {
            acc[0][v] = fmaf(w0, m[v], acc[0][v]);
            acc[1][v] = fmaf(w1, m[v], acc[1][v]);
            acc[2][v] = fmaf(w2, m[v], acc[2][v]);
            acc[3][v] = fmaf(w3, m[v], acc[3][v]);
        }
    }
#pragma unroll
    for (int u = 0; u < 4; u++) {
        float* dst = &out[(size_t)(bt0 + btl + u) * ncols + ij0 + jl];
#pragma unroll
        for (int v = 0; v < 16; v += 4)
            *(float4*)&dst[v] = make_float4(acc[u][v], acc[u][v + 1], acc[u][v + 2], acc[u][v + 3]);
    }
}

// ---------------- forward Kalman filter: one CTA per batch ----------------
struct FwdS {
    float Sig[LL * LL];     // carry: predicted covariance (stride 64)
    float AtT[2][LL * 68];  // A transposed, double-buffered
    float CtT[2][LL * 36];  // C transposed, double-buffered
    float CS[DD * 68];      // CS0 = C@Sig (stride 68)
    float KgT[DD * 68];     // Kg^T (stride 68)
    float T2T[LL * 68];     // (A@Sigz)^T (stride 68)
    float Sigz[LL * LL];
    float Sst[DD * 34];     // S staging (stride 34)
    float P0[2][104];       // GJ raw pivot row p
    float P1[2][104];       // GJ raw pivot row p+1
    float F0[2][DD];        // GJ raw pivot column p
    float F1[2][DD];        // GJ raw pivot column p+1
    float Fd[DD];
    float mu[LL];
    float muz[LL];
    float r[DD];
    float y[2][DD];         // obs, double-buffered
};

extern __shared__ char smem_raw[];

__global__ __launch_bounds__(NT, 1) void fwd_kernel(const float* __restrict__ obs,
                                                    const float* __restrict__ outA,
                                                    const float* __restrict__ outC) {
    FwdS& s = *(FwdS*)smem_raw;
    int tid = threadIdx.x;
    int b = blockIdx.x;
    for (int o = tid; o < LL * LL; o += NT) s.Sig[o] = ((o >> 6) == (o & 63)) ? 20.f : 0.f;
    if (tid < LL) s.mu[tid] = 0.f;

    int it8 = (tid >> 4) * 8;        // i0
    int jt4 = (tid & 15) * 4;        // j0
    int ip4 = (tid >> 4) * 4;
    int sd = tid >> 4;               // 0..31
    int e0 = (tid & 15) * 2;         // 0..30
    int gr = tid / 12;
    int gq = tid - gr * 12;
    int gc = gq * 8;                 // 0..88 (cols 0..31 = S, 32..95 = RHS)
    bool gjA = (tid < 384);
    bool isRHS = gjA && (gc >= 32);
    int c0 = gc - 32;
    int pf = tid - 384;              // prefetch lane 0..127 (tid>=384)

    float v[8];                       // GJ register row-chunk

    // prologue: load A/C/y for t=0 into buffer 0 (all threads)
    {
        const float* Ag = outA + (size_t)(b * TT) * (LL * LL);
        const float* Cg = outC + (size_t)(b * TT) * (DD * LL);
        for (int o = tid * 4; o < LL * LL; o += NT * 4) {
            float4 w = *(const float4*)(Ag + o);
            int i = o >> 6, j = o & 63;
            s.AtT[0][(j + 0) * 68 + i] = w.x;
            s.AtT[0][(j + 1) * 68 + i] = w.y;
            s.AtT[0][(j + 2) * 68 + i] = w.z;
            s.AtT[0][(j + 3) * 68 + i] = w.w;
        }
        int o = tid * 4;
        if (o < DD * LL) {
            float4 w = *(const float4*)&Cg[o];
            int i = o >> 6, j = o & 63;
            s.CtT[0][(j + 0) * 36 + i] = w.x;
            s.CtT[0][(j + 1) * 36 + i] = w.y;
            s.CtT[0][(j + 2) * 36 + i] = w.z;
            s.CtT[0][(j + 3) * 36 + i] = w.w;
        }
        if (tid < DD) s.y[0][tid] = obs[((size_t)b * TT) * DD + tid];
    }
    __syncthreads();

    for (int t = 0; t < TT; t++) {
        int buf = t & 1;
        const float* At = s.AtT[buf];
        const float* Ct = s.CtT[buf];
        const float* Ag1 = outA + (size_t)(b * TT + t + 1) * (LL * LL);
        const float* Cg1 = outC + (size_t)(b * TT + t + 1) * (DD * LL);

        // p2: CS = C @ Sig (32x64) via 4x4 tiles on threads 0..127 ; r = y - C mu on 128..159
        if (tid < 128) {
            u64 acc[4][2];
            zero44(acc);
            mm44<LL, 36, LL, false>(acc, &Ct[ip4], &s.Sig[jt4]);
#pragma unroll
            for (int r2 = 0; r2 < 4; r2++)
                *(ulonglong2*)&s.CS[(ip4 + r2) * 68 + jt4] = make_ulonglong2(acc[r2][0], acc[r2][1]);
        } else if (tid < 160) {
            int m = tid - 128;
            float a = s.y[buf][m];
            for (int l = 0; l < LL; l++) a = fmaf(-Ct[l * 36 + m], s.mu[l], a);
            s.r[m] = a;
        }
        __syncthreads();

        // p3: S = CS0@C^T + 0.3 I
        {
            u64 sacc = pk2((sd == e0) ? 0.3f : 0.f, (sd == e0 + 1) ? 0.3f : 0.f);
            const float* crow = &s.CS[sd * 68];
#pragma unroll 8
            for (int k = 0; k < LL; k++)
                vfma(sacc, splat2(crow[k]), *(const u64*)&Ct[k * 36 + e0]);
            *(u64*)&s.Sst[sd * 34 + e0] = sacc;
        }
        __syncthreads();

        // p3b: GJ threads load register rows; initial publishes for pivot pair 0
        if (gjA) {
            if (gc < 32) {
#pragma unroll
                for (int i = 0; i < 8; i++) v[i] = s.Sst[gr * 34 + gc + i];
            } else {
#pragma unroll
                for (int i = 0; i < 8; i++) v[i] = s.CS[gr * 68 + c0 + i];
            }
            if (gr == 0) {
#pragma unroll
                for (int i = 0; i < 8; i++) s.P0[0][gc + i] = v[i];
            }
            if (gr == 1) {
#pragma unroll
                for (int i = 0; i < 8; i++) s.P1[0][gc + i] = v[i];
            }
            if (gq == 0) { s.F0[0][gr] = v[0]; s.F1[0][gr] = v[1]; }
        }
        __syncthreads();

        // Dual-pivot Gauss-Jordan (2 pivots/sync) with A/C prefetch on idle threads.
        for (int p = 0; p < DD; p += 2) {
            int par = (p >> 1) & 1;
            if (gjA) {
                float d0 = s.P0[par][p];
                float inv0 = __frcp_rn(d0);
                float f0p1 = s.P1[par][p] * inv0;
                float d1 = fmaf(-f0p1, s.P0[par][p + 1], s.P1[par][p + 1]);
                float inv1 = __frcp_rn(d1);
                float f0 = s.F0[par][gr] * inv0;
                float F1eff = (gr == p) ? s.F1[par][gr]
                                        : fmaf(-f0, s.P0[par][p + 1], s.F1[par][gr]);
                float f1 = F1eff * inv1;
                float a0 = (gr == p) ? 0.f : f0;
                float b1 = (gr == p + 1) ? 0.f : f1;
                float b0 = fmaf(-b1, f0p1, a0);
                float4 q0 = *(float4*)&s.P0[par][gc];
                float4 q1 = *(float4*)&s.P0[par][gc + 4];
                float4 r0 = *(float4*)&s.P1[par][gc];
                float4 r1 = *(float4*)&s.P1[par][gc + 4];
                v[0] = fmaf(-b0, q0.x, fmaf(-b1, r0.x, v[0]));
                v[1] = fmaf(-b0, q0.y, fmaf(-b1, r0.y, v[1]));
                v[2] = fmaf(-b0, q0.z, fmaf(-b1, r0.z, v[2]));
                v[3] = fmaf(-b0, q0.w, fmaf(-b1, r0.w, v[3]));
                v[4] = fmaf(-b0, q1.x, fmaf(-b1, r1.x, v[4]));
                v[5] = fmaf(-b0, q1.y, fmaf(-b1, r1.y, v[5]));
                v[6] = fmaf(-b0, q1.z, fmaf(-b1, r1.z, v[6]));
                v[7] = fmaf(-b0, q1.w, fmaf(-b1, r1.w, v[7]));
                int np = p + 2;
                if (np < DD) {
                    if (gr == np) {
#pragma unroll
                        for (int i = 0; i < 8; i++) s.P0[par ^ 1][gc + i] = v[i];
                    }
                    if (gr == np + 1) {
#pragma unroll
                        for (int i = 0; i < 8; i++) s.P1[par ^ 1][gc + i] = v[i];
                    }
                    if (np >= gc && np < gc + 8) {
                        s.F0[par ^ 1][gr] = v[np - gc];
                        s.F1[par ^ 1][gr] = v[np - gc + 1];
                    }
                } else {
#pragma unroll
                    for (int i = 0; i < 8; i++)
                        if (gr == gc + i) s.Fd[gr] = v[i];
                }
            } else if (t + 1 < TT) {
                // prefetch next step's A/C/y into buf^1 (threads 384..511)
                int itr = p >> 1;              // 0..15
                if (itr < 12) {
                    int idx = itr * 128 + pf;  // 0..1535
                    if (idx < 1024) {
                        int o = idx * 4;
                        float4 w = *(const float4*)(Ag1 + o);
                        int i = o >> 6, j = o & 63;
                        s.AtT[buf ^ 1][(j + 0) * 68 + i] = w.x;
                        s.AtT[buf ^ 1][(j + 1) * 68 + i] = w.y;
                        s.AtT[buf ^ 1][(j + 2) * 68 + i] = w.z;
                        s.AtT[buf ^ 1][(j + 3) * 68 + i] = w.w;
                    } else {
                        int o = (idx - 1024) * 4;
                        float4 w = *(const float4*)(Cg1 + o);
                        int i = o >> 6, j = o & 63;
                        s.CtT[buf ^ 1][(j + 0) * 36 + i] = w.x;
                        s.CtT[buf ^ 1][(j + 1) * 36 + i] = w.y;
                        s.CtT[buf ^ 1][(j + 2) * 36 + i] = w.z;
                        s.CtT[buf ^ 1][(j + 3) * 36 + i] = w.w;
                    }
                } else if (itr == 12 && pf < DD) {
                    s.y[buf ^ 1][pf] = obs[((size_t)b * TT + t + 1) * DD + pf];
                }
            }
            __syncthreads();
        }

        // writeout: KgT[m][i] = RHS[m][i] / diag[m]
        if (isRHS) {
            float dinv = __frcp_rn(s.Fd[gr]);
#pragma unroll
            for (int i = 0; i < 8; i += 2)
                *(u64*)&s.KgT[gr * 68 + c0 + i] = pk2(v[i] * dinv, v[i + 1] * dinv);
        }
        __syncthreads();

        // p6: Sigz = Sig - Kg@CS0 ; muz = mu + Kg r
        if (tid < 128) {
            u64 acc[8][2];
            load84<LL>(acc, &s.Sig[it8 * LL + jt4]);
            mm84<DD, 68, 68, true>(acc, &s.KgT[it8], &s.CS[jt4]);
            store84<LL>(&s.Sigz[it8 * LL + jt4], acc);
        } else if (tid < 192) {
            int i = tid - 128;
            float a = s.mu[i];
            for (int m = 0; m < DD; m++) a = fmaf(s.KgT[m * 68 + i], s.r[m], a);
            s.muz[i] = a;
        }
        __syncthreads();

        // p7: T2 = A @ Sigz stored transposed ; others store gmem outputs
        // (g_Sigp[t=0] is never read by jk — skip that store)
        {
            size_t gb = (size_t)t * BB + b;
            if (tid < 128) {
                u64 acc[8][2];
                zero84(acc);
                mm84<LL, 68, LL, false>(acc, &At[it8], &s.Sigz[jt4]);
                storeT84<68>(&s.T2T[jt4 * 68 + it8], acc);
            } else {
                if (tid < 192) {
                    int i = tid - 128;
                    g_muf[gb * LL + i] = s.muz[i];
                    g_mup[gb * LL + i] = s.mu[i];
                }
                bool doP = (t > 0);
                for (int o = 512 + (tid - 128) * 4; o < LL * LL; o += 384 * 4) {
                    *(float4*)&g_Sigf[gb * 4096 + o] = *(float4*)&s.Sigz[o];
                    if (doP) *(float4*)&g_Sigp[gb * 4096 + o] = *(float4*)&s.Sig[o];
                }
                for (int o = (tid - 128) * 4; o < 512; o += 384 * 4) {
                    *(float4*)&g_Sigf[gb * 4096 + o] = *(float4*)&s.Sigz[o];
                    if (doP) *(float4*)&g_Sigp[gb * 4096 + o] = *(float4*)&s.Sig[o];
                }
            }
        }
        __syncthreads();

        // p8: Sig_new = T2 @ A^T + 0.8 I ; mu_new = A muz
        if (tid < 128) {
            u64 acc[8][2];
#pragma unroll
            for (int r2 = 0; r2 < 8; r2++) {
                int i = it8 + r2;
                acc[r2][0] = pk2((i == jt4) ? 0.8f : 0.f, (i == jt4 + 1) ? 0.8f : 0.f);
                acc[r2][1] = pk2((i == jt4 + 2) ? 0.8f : 0.f, (i == jt4 + 3) ? 0.8f : 0.f);
            }
            mm84<LL, 68, 68, false>(acc, &s.T2T[it8], &At[jt4]);
            store84<LL>(&s.Sig[it8 * LL + jt4], acc);
        } else if (tid < 192) {
            int i = tid - 128;
            float a = 0.f;
            for (int k = 0; k < LL; k++) a = fmaf(At[k * 68 + i], s.muz[k], a);
            s.mu[i] = a;
        }
        __syncthreads();
    }
}

// ---------------- J precompute: fully parallel over (b, t) ----------------
struct JkS {
    float sAT[LL * 68];     // A_{t+1} transposed; after GJ reused as X = J^T rows
    float sSf[LL * LL];
    float sRHS[LL * 68];    // RHS = A @ Sf (rows, stride 68)
    float Prow[2][144];
    float Fcol[2][LL];
    float Fd[LL];
    float smf[LL];
    float smp[LL];
};

__global__ __launch_bounds__(NT, 2) void jk_kernel(const float* __restrict__ outA) {
    JkS& s = *(JkS*)smem_raw;
    int tid = threadIdx.x;
    int b = blockIdx.x;
    int t = blockIdx.y;                     // 0..T-2
    size_t gf = (size_t)t * BB + b;
    size_t gp = (size_t)(t + 1) * BB + b;

    int it8 = (tid >> 4) * 8;
    int jt4 = (tid & 15) * 4;

    int gr = tid >> 3;                      // 0..63
    int gq = tid & 7;
    int gc = gq * 16;                       // 0..112 (cols 0..63 = Sp, 64..127 = RHS)
    bool isRHS = (gc >= 64);
    int c0 = gc - 64;

    const float* Ag = outA + ((size_t)b * TT + (t + 1)) * (LL * LL);
    for (int o = tid * 4; o < LL * LL; o += NT * 4) {
        float4 w = *(const float4*)(Ag + o);
        int i = o >> 6, j = o & 63;
        s.sAT[(j + 0) * 68 + i] = w.x;
        s.sAT[(j + 1) * 68 + i] = w.y;
        s.sAT[(j + 2) * 68 + i] = w.z;
        s.sAT[(j + 3) * 68 + i] = w.w;
        *(float4*)&s.sSf[o] = *(const float4*)&g_Sigf[gf * 4096 + o];
    }
    if (tid < LL) s.smf[tid] = g_muf[gf * LL + tid];
    else if (tid < 2 * LL) s.smp[tid - LL] = g_mup[gp * LL + (tid - LL)];
    __syncthreads();

    // RHS = A @ Sf via 8x4 tiles (threads 0..127)
    if (tid < 128) {
        u64 acc[8][2];
        zero84(acc);
        mm84<LL, 68, LL, false>(acc, &s.sAT[it8], &s.sSf[jt4]);
        store84<68>(&s.sRHS[it8 * 68 + jt4], acc);
    }
    __syncthreads();

    float v[16];
    if (isRHS) {
#pragma unroll
        for (int i = 0; i < 16; i += 4) *(float4*)&v[i] = *(const float4*)&s.sRHS[gr * 68 + c0 + i];
    } else {
        const float* sp = &g_Sigp[gp * 4096 + gr * LL + gc];
#pragma unroll
        for (int i = 0; i < 16; i += 4) *(float4*)&v[i] = *(const float4*)&sp[i];
    }
    if (gr == 0) {
#pragma unroll
        for (int i = 0; i < 16; i++) s.Prow[0][gc + i] = v[i];
    }
    if (gq == 0) s.Fcol[0][gr] = v[0];
    __syncthreads();

    for (int p = 0; p < LL; p++) {
        int par = p & 1;
        float inv = __frcp_rn(s.Fcol[par][p]);
        float f = s.Fcol[par][gr] * inv;
        float4 p0 = *(float4*)&s.Prow[par][gc];
        float4 p1 = *(float4*)&s.Prow[par][gc + 4];
        float4 p2 = *(float4*)&s.Prow[par][gc + 8];
        float4 p3 = *(float4*)&s.Prow[par][gc + 12];
        if (gr != p) {
            v[0] = fmaf(-f, p0.x, v[0]);  v[1] = fmaf(-f, p0.y, v[1]);
            v[2] = fmaf(-f, p0.z, v[2]);  v[3] = fmaf(-f, p0.w, v[3]);
            v[4] = fmaf(-f, p1.x, v[4]);  v[5] = fmaf(-f, p1.y, v[5]);
            v[6] = fmaf(-f, p1.z, v[6]);  v[7] = fmaf(-f, p1.w, v[7]);
            v[8] = fmaf(-f, p2.x, v[8]);  v[9] = fmaf(-f, p2.y, v[9]);
            v[10] = fmaf(-f, p2.z, v[10]); v[11] = fmaf(-f, p2.w, v[11]);
            v[12] = fmaf(-f, p3.x, v[12]); v[13] = fmaf(-f, p3.y, v[13]);
            v[14] = fmaf(-f, p3.z, v[14]); v[15] = fmaf(-f, p3.w, v[15]);
        }
        int np = p + 1;
        if (np < LL) {
            if (gr == np) {
#pragma unroll
                for (int i = 0; i < 16; i++) s.Prow[par ^ 1][gc + i] = v[i];
            }
#pragma unroll
            for (int i = 0; i < 16; i++)
                if (np == gc + i) s.Fcol[par ^ 1][gr] = v[i];
        } else {
#pragma unroll
            for (int i = 0; i < 16; i++)
                if (gr == gc + i) s.Fd[gr] = v[i];
        }
        __syncthreads();
    }

    // X = J^T rows: write to g_J and into sAT (reused; A dead)
    if (isRHS) {
        float dinv = __frcp_rn(s.Fd[gr]);
        float* dst = &g_J[gf * 4096 + gr * LL + c0];
#pragma unroll
        for (int i = 0; i < 16; i += 4) {
            float4 w = make_float4(v[i] * dinv, v[i + 1] * dinv, v[i + 2] * dinv, v[i + 3] * dinv);
            *(float4*)&dst[i] = w;
            *(float4*)&s.sAT[gr * 68 + c0 + i] = w;
        }
    }
    __syncthreads();

    // B_t = Sf - RHS^T @ X (8x4 tiles) ; b_t = mf - J mp1
    if (tid < 128) {
        u64 acc[8][2];
        load84<LL>(acc, &s.sSf[it8 * LL + jt4]);
        mm84<LL, 68, 68, true>(acc, &s.sRHS[it8], &s.sAT[jt4]);
        store84<LL>(&g_B[gf * 4096 + it8 * LL + jt4], acc);
    } else if (tid < 192) {
        int i = tid - 128;
        float a = s.smf[i];
        for (int m = 0; m < LL; m++) a = fmaf(-s.sAT[m * 68 + i], s.smp[m], a);
        g_bv[gf * LL + i] = a;
    }
}

// ---------------- backward RTS recursion with smem prefetch ----------------
struct BwdS {
    float Sigs[LL * LL];    // carry: smoothed cov at t+1 (stride 64)
    float sX[2][LL * LL];   // X = J^T rows, double buffered
    float sB[LL * LL];      // B_t prefetch
    float T1T[LL * 68];     // (J@Sigs)^T
    float mus[LL];
    float musN[LL];
    float bv[2][LL];
};

__global__ __launch_bounds__(NT, 1) void bwd_kernel(float* __restrict__ outMu,
                                                    float* __restrict__ outSig) {
    BwdS& s = *(BwdS*)smem_raw;
    int tid = threadIdx.x;
    int b = blockIdx.x;
    int it8 = (tid >> 4) * 8;
    int jt4 = (tid & 15) * 4;

    {
        size_t gb = (size_t)(TT - 1) * BB + b;
        size_t g0 = (size_t)(TT - 2) * BB + b;
        for (int o = tid * 4; o < LL * LL; o += NT * 4) {
            float4 w = *(const float4*)&g_Sigf[gb * 4096 + o];
            *(float4*)&s.Sigs[o] = w;
            *(float4*)&outSig[gb * 4096 + o] = w;
            *(float4*)&s.sX[0][o] = *(const float4*)&g_J[g0 * 4096 + o];
        }
        if (tid < LL) {
            float w = g_muf[gb * LL + tid];
            s.mus[tid] = w;
            outMu[gb * LL + tid] = w;
            s.bv[0][tid] = g_bv[g0 * LL + tid];
        }
    }
    __syncthreads();

    for (int t = TT - 2; t >= 0; t--) {
        int cur = (TT - 2 - t) & 1;
        size_t gf = (size_t)t * BB + b;

        // m1: T1 = J @ Sigs (0..127) ; mu_s (128..191) ; prefetch B_t (192..447)
        if (tid < 128) {
            u64 acc[8][2];
            zero84(acc);
            mm84<LL, LL, LL, false>(acc, &s.sX[cur][it8], &s.Sigs[jt4]);
            storeT84<68>(&s.T1T[jt4 * 68 + it8], acc);
        } else if (tid < 192) {
            int i = tid - 128;
            float a = s.bv[cur][i];
            for (int k = 0; k < LL; k++) a = fmaf(s.sX[cur][k * LL + i], s.mus[k], a);
            s.musN[i] = a;
            outMu[gf * LL + i] = a;
        } else if (tid < 448) {
            for (int o = (tid - 192) * 4; o < LL * LL; o += 256 * 4)
                *(float4*)&s.sB[o] = *(const float4*)&g_B[gf * 4096 + o];
        }
        __syncthreads();

        // m2: Sigs_new = B + T1 @ X (0..127) ; mus copy (128..191) ; prefetch J/bv t-1 (192..511)
        if (tid < 128) {
            u64 acc[8][2];
            load84<LL>(acc, &s.sB[it8 * LL + jt4]);
            mm84<LL, 68, LL, false>(acc, &s.T1T[it8], &s.sX[cur][jt4]);
            store84<LL>(&s.Sigs[it8 * LL + jt4], acc);
            store84<LL>(&outSig[gf * 4096 + it8 * LL + jt4], acc);
        } else if (tid < 192) {
            s.mus[tid - 128] = s.musN[tid - 128];
        } else if (t > 0) {
            size_t gn = (size_t)(t - 1) * BB + b;
            if (tid < 448) {
                for (int o = (tid - 192) * 4; o < LL * LL; o += 256 * 4)
                    *(float4*)&s.sX[cur ^ 1][o] = *(const float4*)&g_J[gn * 4096 + o];
            } else {
                s.bv[cur ^ 1][tid - 448] = g_bv[gn * LL + (tid - 448)];
            }
        }
        __syncthreads();
    }
}

// ---------------- launch ----------------
extern "C" void kernel_launch(void* const* d_in, const int* in_sizes, int n_in,
                              void* d_out, int out_size) {
    const float* obs   = (const float*)d_in[0];
    const float* start = (const float*)d_in[1];
    const float* W1    = (const float*)d_in[2];
    const float* b1    = (const float*)d_in[3];
    const float* W2    = (const float*)d_in[4];
    const float* b2    = (const float*)d_in[5];
    const float* A     = (const float*)d_in[6];
    const float* C     = (const float*)d_in[7];

    float* out = (float*)d_out;
    float* outMu  = out;                                   // (T,B,L)      409600
    float* outSig = out + 409600;                          // (T,B,L,L)  26214400
    float* outA   = out + 26624000;                        // (B,T,L,L)  26214400
    float* outC   = out + 52838400;                        // (B,T,D,L)  13107200

    cudaFuncSetAttribute(fwd_kernel, cudaFuncAttributeMaxDynamicSharedMemorySize, (int)sizeof(FwdS));
    cudaFuncSetAttribute(jk_kernel, cudaFuncAttributeMaxDynamicSharedMemorySize, (int)sizeof(JkS));
    cudaFuncSetAttribute(bwd_kernel, cudaFuncAttributeMaxDynamicSharedMemorySize, (int)sizeof(BwdS));

    w_kernel<<<BB * TT, 64>>>(obs, start, W1, b1, W2, b2);

    dim3 gA(4096 / 512, BB * TT / 32);
    mix_kernel<<<gA, 256>>>(A, outA, 4096);
    dim3 gC(2048 / 512, BB * TT / 32);
    mix_kernel<<<gC, 256>>>(C, outC, 2048);

    fwd_kernel<<<BB, NT, sizeof(FwdS)>>>(obs, outA, outC);

    dim3 gJ(BB, TT - 1);
    jk_kernel<<<gJ, NT, sizeof(JkS)>>>(outA);

    bwd_kernel<<<BB, NT, sizeof(BwdS)>>>(outMu, outSig);
}

// round 17
// speedup vs baseline: 1.2706x; 1.2469x over previous
#include <cuda_runtime.h>

#define BB 64
#define TT 100
#define DD 32
#define LL 64
#define KK 16
#define HH 50
#define NT 512

typedef unsigned long long u64;

// ---------------- global scratch (no allocation allowed) ----------------
__device__ float g_w[BB * TT * KK];
__device__ float g_muf[BB * TT * LL];
__device__ float g_mup[BB * TT * LL];
__device__ float g_Sigf[(size_t)BB * TT * LL * LL];
__device__ float g_Sigp[(size_t)BB * TT * LL * LL];
__device__ float g_J[(size_t)BB * (TT - 1) * LL * LL];    // X = J^T per (t,b)
__device__ float g_B[(size_t)BB * (TT - 1) * LL * LL];    // B_t = Sf - J Sp J^T
__device__ float g_bv[(size_t)BB * (TT - 1) * LL];        // b_t = mf - J mp1

// ---------------- packed f32x2 helpers ----------------
__device__ __forceinline__ u64 splat2(float a) {
    u64 r; asm("mov.b64 %0, {%1,%1};" : "=l"(r) : "f"(a)); return r;
}
__device__ __forceinline__ u64 pk2(float x, float y) {
    u64 r; asm("mov.b64 %0, {%1,%2};" : "=l"(r) : "f"(x), "f"(y)); return r;
}
__device__ __forceinline__ float2 unpk(u64 v) {
    float2 r; asm("mov.b64 {%0,%1}, %2;" : "=f"(r.x), "=f"(r.y) : "l"(v)); return r;
}
__device__ __forceinline__ void vfma(u64& d, u64 a, u64 b) {
    asm("fma.rn.f32x2 %0, %1, %2, %0;" : "+l"(d) : "l"(a), "l"(b));
}

// ---- 8x4 register-tile matmul ----
template<int KN, int SA, int SB, bool NEG>
__device__ __forceinline__ void mm84(u64 acc[8][2], const float* __restrict__ aT,
                                     const float* __restrict__ bB) {
#pragma unroll 16
    for (int k = 0; k < KN; k++) {
        float4 a0 = *(const float4*)(aT + k * SA);
        float4 a1 = *(const float4*)(aT + k * SA + 4);
        ulonglong2 bv = *(const ulonglong2*)(bB + k * SB);
        u64 s;
        s = splat2(NEG ? -a0.x : a0.x); vfma(acc[0][0], s, bv.x); vfma(acc[0][1], s, bv.y);
        s = splat2(NEG ? -a0.y : a0.y); vfma(acc[1][0], s, bv.x); vfma(acc[1][1], s, bv.y);
        s = splat2(NEG ? -a0.z : a0.z); vfma(acc[2][0], s, bv.x); vfma(acc[2][1], s, bv.y);
        s = splat2(NEG ? -a0.w : a0.w); vfma(acc[3][0], s, bv.x); vfma(acc[3][1], s, bv.y);
        s = splat2(NEG ? -a1.x : a1.x); vfma(acc[4][0], s, bv.x); vfma(acc[4][1], s, bv.y);
        s = splat2(NEG ? -a1.y : a1.y); vfma(acc[5][0], s, bv.x); vfma(acc[5][1], s, bv.y);
        s = splat2(NEG ? -a1.z : a1.z); vfma(acc[6][0], s, bv.x); vfma(acc[6][1], s, bv.y);
        s = splat2(NEG ? -a1.w : a1.w); vfma(acc[7][0], s, bv.x); vfma(acc[7][1], s, bv.y);
    }
}

__device__ __forceinline__ void zero84(u64 acc[8][2]) {
#pragma unroll
    for (int r = 0; r < 8; r++) { acc[r][0] = 0ull; acc[r][1] = 0ull; }
}
template<int SS>
__device__ __forceinline__ void load84(u64 acc[8][2], const float* src) {
#pragma unroll
    for (int r = 0; r < 8; r++) {
        ulonglong2 w = *(const ulonglong2*)(src + r * SS);
        acc[r][0] = w.x; acc[r][1] = w.y;
    }
}
template<int SS>
__device__ __forceinline__ void store84(float* dst, const u64 acc[8][2]) {
#pragma unroll
    for (int r = 0; r < 8; r++)
        *(ulonglong2*)(dst + r * SS) = make_ulonglong2(acc[r][0], acc[r][1]);
}
template<int SD>
__device__ __forceinline__ void storeT84(float* dstT, const u64 acc[8][2]) {
    float va[8][4];
#pragma unroll
    for (int r = 0; r < 8; r++) {
        float2 e0 = unpk(acc[r][0]);
        float2 e1 = unpk(acc[r][1]);
        va[r][0] = e0.x; va[r][1] = e0.y; va[r][2] = e1.x; va[r][3] = e1.y;
    }
#pragma unroll
    for (int c = 0; c < 4; c++) {
        *(ulonglong2*)(dstT + c * SD) =
            make_ulonglong2(pk2(va[0][c], va[1][c]), pk2(va[2][c], va[3][c]));
        *(ulonglong2*)(dstT + c * SD + 4) =
            make_ulonglong2(pk2(va[4][c], va[5][c]), pk2(va[6][c], va[7][c]));
    }
}

// ---- 4x4 tile (for 32-row outputs) ----
template<int KN, int SA, int SB, bool NEG>
__device__ __forceinline__ void mm44(u64 acc[4][2], const float* __restrict__ aT,
                                     const float* __restrict__ bB) {
#pragma unroll 16
    for (int k = 0; k < KN; k++) {
        float4 a0 = *(const float4*)(aT + k * SA);
        ulonglong2 bv = *(const ulonglong2*)(bB + k * SB);
        u64 s;
        s = splat2(NEG ? -a0.x : a0.x); vfma(acc[0][0], s, bv.x); vfma(acc[0][1], s, bv.y);
        s = splat2(NEG ? -a0.y : a0.y); vfma(acc[1][0], s, bv.x); vfma(acc[1][1], s, bv.y);
        s = splat2(NEG ? -a0.z : a0.z); vfma(acc[2][0], s, bv.x); vfma(acc[2][1], s, bv.y);
        s = splat2(NEG ? -a0.w : a0.w); vfma(acc[3][0], s, bv.x); vfma(acc[3][1], s, bv.y);
    }
}
__device__ __forceinline__ void zero44(u64 acc[4][2]) {
#pragma unroll
    for (int r = 0; r < 4; r++) { acc[r][0] = 0ull; acc[r][1] = 0ull; }
}

// ---------------- kernel 1: mixing weights w = softmax(MLP(joint)) ----------------
__global__ void w_kernel(const float* __restrict__ obs, const float* __restrict__ start,
                         const float* __restrict__ W1, const float* __restrict__ b1,
                         const float* __restrict__ W2, const float* __restrict__ b2) {
    __shared__ float sj[DD];
    __shared__ float sh[HH];
    __shared__ float se[KK];
    int bt = blockIdx.x;
    int b = bt / TT, t = bt % TT;
    int tid = threadIdx.x;
    if (tid < DD) sj[tid] = (t == 0) ? start[tid] : obs[((size_t)b * TT + t - 1) * DD + tid];
    __syncthreads();
    if (tid < HH) {
        float a = b1[tid];
        for (int d = 0; d < DD; d++) a = fmaf(sj[d], W1[d * HH + tid], a);
        sh[tid] = fmaxf(a, 0.f);
    }
    __syncthreads();
    if (tid < KK) {
        float a = b2[tid];
        for (int j = 0; j < HH; j++) a = fmaf(sh[j], W2[j * KK + tid], a);
        se[tid] = a;
    }
    __syncthreads();
    if (tid == 0) {
        float m = se[0];
        for (int k = 1; k < KK; k++) m = fmaxf(m, se[k]);
        float ex[KK];
        float ssum = 0.f;
        for (int k = 0; k < KK; k++) { ex[k] = expf(se[k] - m); ssum += ex[k]; }
        float inv = 1.f / ssum;
        for (int k = 0; k < KK; k++) g_w[bt * KK + k] = ex[k] * inv;
    }
}

// ---------------- kernel 2: A_t / C_t mixing ----------------
__global__ void mix_kernel(const float* __restrict__ M, float* __restrict__ out, int ncols) {
    __shared__ float sM[KK * 512];
    __shared__ float sw[32 * KK];
    int tid = threadIdx.x;
    int ij0 = blockIdx.x * 512;
    int bt0 = blockIdx.y * 32;
    for (int idx = tid * 4; idx < KK * 512; idx += 256 * 4) {
        int k = idx / 512, c = idx % 512;
        *(float4*)&sM[idx] = *(const float4*)&M[(size_t)k * ncols + ij0 + c];
    }
    sw[tid]       = g_w[bt0 * KK + tid];
    sw[tid + 256] = g_w[bt0 * KK + tid + 256];
    __syncthreads();

    int btl = (tid >> 5) * 4;
    int jl  = (tid & 31) * 16;
    float acc[4][16];
#pragma unroll
    for (int u = 0; u < 4; u++)
#pragma unroll
        for (int v = 0; v < 16; v++) acc[u][v] = 0.f;

    for (int k = 0; k < KK; k++) {
        float w0 = sw[(btl + 0) * KK + k];
        float w1 = sw[(btl + 1) * KK + k];
        float w2 = sw[(btl + 2) * KK + k];
        float w3 = sw[(btl + 3) * KK + k];
        float m[16];
#pragma unroll
        for (int v = 0; v < 16; v += 4) *(float4*)&m[v] = *(float4*)&sM[k * 512 + jl + v];
#pragma unroll
        for (int v = 0; v < 16; v++) {
            acc[0][v] = fmaf(w0, m[v], acc[0][v]);
            acc[1][v] = fmaf(w1, m[v], acc[1][v]);
            acc[2][v] = fmaf(w2, m[v], acc[2][v]);
            acc[3][v] = fmaf(w3, m[v], acc[3][v]);
        }
    }
#pragma unroll
    for (int u = 0; u < 4; u++) {
        float* dst = &out[(size_t)(bt0 + btl + u) * ncols + ij0 + jl];
#pragma unroll
        for (int v = 0; v < 16; v += 4)
            *(float4*)&dst[v] = make_float4(acc[u][v], acc[u][v + 1], acc[u][v + 2], acc[u][v + 3]);
    }
}

// ---------------- forward Kalman filter: one CTA per batch ----------------
struct FwdS {
    float Sig[LL * LL];     // carry: predicted covariance (stride 64)
    float AtT[2][LL * 68];  // A transposed, double-buffered
    float CtT[2][LL * 36];  // C transposed, double-buffered
    float CS[DD * 68];      // CS0 = C@Sig (stride 68)
    float KgT[DD * 68];     // Kg^T (stride 68)
    float T2T[LL * 68];     // (A@Sigz)^T (stride 68)
    float Sigz[LL * LL];
    float Sst[DD * 34];     // S staging (stride 34)
    float P0[2][104];       // GJ raw pivot row p
    float P1[2][104];       // GJ raw pivot row p+1
    float F0[2][DD];        // GJ raw pivot column p
    float F1[2][DD];        // GJ raw pivot column p+1
    float Fd[DD];
    float mu[LL];
    float muz[LL];
    float r[DD];
    float y[2][DD];         // obs, double-buffered
};

extern __shared__ char smem_raw[];

__global__ __launch_bounds__(NT, 1) void fwd_kernel(const float* __restrict__ obs,
                                                    const float* __restrict__ outA,
                                                    const float* __restrict__ outC) {
    FwdS& s = *(FwdS*)smem_raw;
    int tid = threadIdx.x;
    int b = blockIdx.x;
    for (int o = tid; o < LL * LL; o += NT) s.Sig[o] = ((o >> 6) == (o & 63)) ? 20.f : 0.f;
    if (tid < LL) s.mu[tid] = 0.f;

    int it8 = (tid >> 4) * 8;        // i0
    int jt4 = (tid & 15) * 4;        // j0
    int ip4 = (tid >> 4) * 4;
    int sd = tid >> 4;               // 0..31
    int e0 = (tid & 15) * 2;         // 0..30
    int gr = tid / 12;
    int gq = tid - gr * 12;
    int gc = gq * 8;                 // 0..88 (cols 0..31 = S, 32..95 = RHS)
    bool gjA = (tid < 384);
    bool isRHS = gjA && (gc >= 32);
    int c0 = gc - 32;
    int pf = tid - 384;              // prefetch lane 0..127 (tid>=384)

    float v[8];                       // GJ register row-chunk

    // prologue: load A/C/y for t=0 into buffer 0 (all threads)
    {
        const float* Ag = outA + (size_t)(b * TT) * (LL * LL);
        const float* Cg = outC + (size_t)(b * TT) * (DD * LL);
        for (int o = tid * 4; o < LL * LL; o += NT * 4) {
            float4 w = *(const float4*)(Ag + o);
            int i = o >> 6, j = o & 63;
            s.AtT[0][(j + 0) * 68 + i] = w.x;
            s.AtT[0][(j + 1) * 68 + i] = w.y;
            s.AtT[0][(j + 2) * 68 + i] = w.z;
            s.AtT[0][(j + 3) * 68 + i] = w.w;
        }
        int o = tid * 4;
        if (o < DD * LL) {
            float4 w = *(const float4*)&Cg[o];
            int i = o >> 6, j = o & 63;
            s.CtT[0][(j + 0) * 36 + i] = w.x;
            s.CtT[0][(j + 1) * 36 + i] = w.y;
            s.CtT[0][(j + 2) * 36 + i] = w.z;
            s.CtT[0][(j + 3) * 36 + i] = w.w;
        }
        if (tid < DD) s.y[0][tid] = obs[((size_t)b * TT) * DD + tid];
    }
    __syncthreads();

    for (int t = 0; t < TT; t++) {
        int buf = t & 1;
        const float* At = s.AtT[buf];
        const float* Ct = s.CtT[buf];
        const float* Ag1 = outA + (size_t)(b * TT + t + 1) * (LL * LL);
        const float* Cg1 = outC + (size_t)(b * TT + t + 1) * (DD * LL);

        // p2: CS = C @ Sig (32x64) via 4x4 tiles on threads 0..127 ; r = y - C mu on 128..159
        if (tid < 128) {
            u64 acc[4][2];
            zero44(acc);
            mm44<LL, 36, LL, false>(acc, &Ct[ip4], &s.Sig[jt4]);
#pragma unroll
            for (int r2 = 0; r2 < 4; r2++)
                *(ulonglong2*)&s.CS[(ip4 + r2) * 68 + jt4] = make_ulonglong2(acc[r2][0], acc[r2][1]);
        } else if (tid < 160) {
            int m = tid - 128;
            float a = s.y[buf][m];
            for (int l = 0; l < LL; l++) a = fmaf(-Ct[l * 36 + m], s.mu[l], a);
            s.r[m] = a;
        }
        __syncthreads();

        // p3: S = CS0@C^T + 0.3 I
        {
            u64 sacc = pk2((sd == e0) ? 0.3f : 0.f, (sd == e0 + 1) ? 0.3f : 0.f);
            const float* crow = &s.CS[sd * 68];
#pragma unroll 8
            for (int k = 0; k < LL; k++)
                vfma(sacc, splat2(crow[k]), *(const u64*)&Ct[k * 36 + e0]);
            *(u64*)&s.Sst[sd * 34 + e0] = sacc;
        }
        __syncthreads();

        // p3b: GJ threads load register rows; initial publishes for pivot pair 0
        if (gjA) {
            if (gc < 32) {
#pragma unroll
                for (int i = 0; i < 8; i++) v[i] = s.Sst[gr * 34 + gc + i];
            } else {
#pragma unroll
                for (int i = 0; i < 8; i++) v[i] = s.CS[gr * 68 + c0 + i];
            }
            if (gr == 0) {
#pragma unroll
                for (int i = 0; i < 8; i++) s.P0[0][gc + i] = v[i];
            }
            if (gr == 1) {
#pragma unroll
                for (int i = 0; i < 8; i++) s.P1[0][gc + i] = v[i];
            }
            if (gq == 0) { s.F0[0][gr] = v[0]; s.F1[0][gr] = v[1]; }
        }
        __syncthreads();

        // Dual-pivot Gauss-Jordan (2 pivots/sync) with A/C prefetch on idle threads.
        for (int p = 0; p < DD; p += 2) {
            int par = (p >> 1) & 1;
            if (gjA) {
                float d0 = s.P0[par][p];
                float inv0 = __frcp_rn(d0);
                float f0p1 = s.P1[par][p] * inv0;
                float d1 = fmaf(-f0p1, s.P0[par][p + 1], s.P1[par][p + 1]);
                float inv1 = __frcp_rn(d1);
                float f0 = s.F0[par][gr] * inv0;
                float F1eff = (gr == p) ? s.F1[par][gr]
                                        : fmaf(-f0, s.P0[par][p + 1], s.F1[par][gr]);
                float f1 = F1eff * inv1;
                float a0 = (gr == p) ? 0.f : f0;
                float b1 = (gr == p + 1) ? 0.f : f1;
                float b0 = fmaf(-b1, f0p1, a0);
                float4 q0 = *(float4*)&s.P0[par][gc];
                float4 q1 = *(float4*)&s.P0[par][gc + 4];
                float4 r0 = *(float4*)&s.P1[par][gc];
                float4 r1 = *(float4*)&s.P1[par][gc + 4];
                v[0] = fmaf(-b0, q0.x, fmaf(-b1, r0.x, v[0]));
                v[1] = fmaf(-b0, q0.y, fmaf(-b1, r0.y, v[1]));
                v[2] = fmaf(-b0, q0.z, fmaf(-b1, r0.z, v[2]));
                v[3] = fmaf(-b0, q0.w, fmaf(-b1, r0.w, v[3]));
                v[4] = fmaf(-b0, q1.x, fmaf(-b1, r1.x, v[4]));
                v[5] = fmaf(-b0, q1.y, fmaf(-b1, r1.y, v[5]));
                v[6] = fmaf(-b0, q1.z, fmaf(-b1, r1.z, v[6]));
                v[7] = fmaf(-b0, q1.w, fmaf(-b1, r1.w, v[7]));
                int np = p + 2;
                if (np < DD) {
                    if (gr == np) {
#pragma unroll
                        for (int i = 0; i < 8; i++) s.P0[par ^ 1][gc + i] = v[i];
                    }
                    if (gr == np + 1) {
#pragma unroll
                        for (int i = 0; i < 8; i++) s.P1[par ^ 1][gc + i] = v[i];
                    }
                    if (np >= gc && np < gc + 8) {
                        s.F0[par ^ 1][gr] = v[np - gc];
                        s.F1[par ^ 1][gr] = v[np - gc + 1];
                    }
                } else {
#pragma unroll
                    for (int i = 0; i < 8; i++)
                        if (gr == gc + i) s.Fd[gr] = v[i];
                }
            } else if (t + 1 < TT) {
                // prefetch next step's A/C/y into buf^1 (threads 384..511)
                int itr = p >> 1;              // 0..15
                if (itr < 12) {
                    int idx = itr * 128 + pf;  // 0..1535
                    if (idx < 1024) {
                        int o = idx * 4;
                        float4 w = *(const float4*)(Ag1 + o);
                        int i = o >> 6, j = o & 63;
                        s.AtT[buf ^ 1][(j + 0) * 68 + i] = w.x;
                        s.AtT[buf ^ 1][(j + 1) * 68 + i] = w.y;
                        s.AtT[buf ^ 1][(j + 2) * 68 + i] = w.z;
                        s.AtT[buf ^ 1][(j + 3) * 68 + i] = w.w;
                    } else {
                        int o = (idx - 1024) * 4;
                        float4 w = *(const float4*)(Cg1 + o);
                        int i = o >> 6, j = o & 63;
                        s.CtT[buf ^ 1][(j + 0) * 36 + i] = w.x;
                        s.CtT[buf ^ 1][(j + 1) * 36 + i] = w.y;
                        s.CtT[buf ^ 1][(j + 2) * 36 + i] = w.z;
                        s.CtT[buf ^ 1][(j + 3) * 36 + i] = w.w;
                    }
                } else if (itr == 12 && pf < DD) {
                    s.y[buf ^ 1][pf] = obs[((size_t)b * TT + t + 1) * DD + pf];
                }
            }
            __syncthreads();
        }

        // writeout: KgT[m][i] = RHS[m][i] / diag[m]
        if (isRHS) {
            float dinv = __frcp_rn(s.Fd[gr]);
#pragma unroll
            for (int i = 0; i < 8; i += 2)
                *(u64*)&s.KgT[gr * 68 + c0 + i] = pk2(v[i] * dinv, v[i + 1] * dinv);
        }
        __syncthreads();

        // p6: Sigz = Sig - Kg@CS0 ; muz = mu + Kg r
        if (tid < 128) {
            u64 acc[8][2];
            load84<LL>(acc, &s.Sig[it8 * LL + jt4]);
            mm84<DD, 68, 68, true>(acc, &s.KgT[it8], &s.CS[jt4]);
            store84<LL>(&s.Sigz[it8 * LL + jt4], acc);
        } else if (tid < 192) {
            int i = tid - 128;
            float a = s.mu[i];
            for (int m = 0; m < DD; m++) a = fmaf(s.KgT[m * 68 + i], s.r[m], a);
            s.muz[i] = a;
        }
        __syncthreads();

        // p7: T2 = A @ Sigz stored transposed ; others store gmem outputs
        {
            size_t gb = (size_t)t * BB + b;
            if (tid < 128) {
                u64 acc[8][2];
                zero84(acc);
                mm84<LL, 68, LL, false>(acc, &At[it8], &s.Sigz[jt4]);
                storeT84<68>(&s.T2T[jt4 * 68 + it8], acc);
            } else {
                if (tid < 192) {
                    int i = tid - 128;
                    g_muf[gb * LL + i] = s.muz[i];
                    g_mup[gb * LL + i] = s.mu[i];
                }
                bool doP = (t > 0);
                for (int o = 512 + (tid - 128) * 4; o < LL * LL; o += 384 * 4) {
                    *(float4*)&g_Sigf[gb * 4096 + o] = *(float4*)&s.Sigz[o];
                    if (doP) *(float4*)&g_Sigp[gb * 4096 + o] = *(float4*)&s.Sig[o];
                }
                for (int o = (tid - 128) * 4; o < 512; o += 384 * 4) {
                    *(float4*)&g_Sigf[gb * 4096 + o] = *(float4*)&s.Sigz[o];
                    if (doP) *(float4*)&g_Sigp[gb * 4096 + o] = *(float4*)&s.Sig[o];
                }
            }
        }
        __syncthreads();

        // p8: Sig_new = T2 @ A^T + 0.8 I ; mu_new = A muz
        if (tid < 128) {
            u64 acc[8][2];
#pragma unroll
            for (int r2 = 0; r2 < 8; r2++) {
                int i = it8 + r2;
                acc[r2][0] = pk2((i == jt4) ? 0.8f : 0.f, (i == jt4 + 1) ? 0.8f : 0.f);
                acc[r2][1] = pk2((i == jt4 + 2) ? 0.8f : 0.f, (i == jt4 + 3) ? 0.8f : 0.f);
            }
            mm84<LL, 68, 68, false>(acc, &s.T2T[it8], &At[jt4]);
            store84<LL>(&s.Sig[it8 * LL + jt4], acc);
        } else if (tid < 192) {
            int i = tid - 128;
            float a = 0.f;
            for (int k = 0; k < LL; k++) a = fmaf(At[k * 68 + i], s.muz[k], a);
            s.mu[i] = a;
        }
        __syncthreads();
    }
}

// ---------------- J precompute: fully parallel over (b, t) ----------------
// Inverts Sp in place (64-wide GJ, v[8]/thread), then X = Sp^{-1} @ RHS via tiles.
struct JkS {
    float sAT[LL * 68];     // A_{t+1} transposed; after GJ reused as X = J^T rows
    float sSf[LL * LL];
    float sRHS[LL * 68];    // RHS = A @ Sf (rows, stride 68)
    float sMI[LL * LL];     // Sp^{-1} (symmetric, row-major stride 64)
    float Prow[2][72];
    float Fcol[2][LL];
    float smf[LL];
    float smp[LL];
};

__global__ __launch_bounds__(NT, 2) void jk_kernel(const float* __restrict__ outA) {
    JkS& s = *(JkS*)smem_raw;
    int tid = threadIdx.x;
    int b = blockIdx.x;
    int t = blockIdx.y;                     // 0..T-2
    size_t gf = (size_t)t * BB + b;
    size_t gp = (size_t)(t + 1) * BB + b;

    int it8 = (tid >> 4) * 8;
    int jt4 = (tid & 15) * 4;

    int gr = tid >> 3;                      // row 0..63
    int gq = tid & 7;
    int gc = gq * 8;                        // col 0..56 (8 cols per thread)

    const float* Ag = outA + ((size_t)b * TT + (t + 1)) * (LL * LL);
    for (int o = tid * 4; o < LL * LL; o += NT * 4) {
        float4 w = *(const float4*)(Ag + o);
        int i = o >> 6, j = o & 63;
        s.sAT[(j + 0) * 68 + i] = w.x;
        s.sAT[(j + 1) * 68 + i] = w.y;
        s.sAT[(j + 2) * 68 + i] = w.z;
        s.sAT[(j + 3) * 68 + i] = w.w;
        *(float4*)&s.sSf[o] = *(const float4*)&g_Sigf[gf * 4096 + o];
    }
    if (tid < LL) s.smf[tid] = g_muf[gf * LL + tid];
    else if (tid < 2 * LL) s.smp[tid - LL] = g_mup[gp * LL + (tid - LL)];

    // GJ registers: load Sp row chunk (all 512 threads)
    float v[8];
    {
        const float* sp = &g_Sigp[gp * 4096 + gr * LL + gc];
        *(float4*)&v[0] = *(const float4*)&sp[0];
        *(float4*)&v[4] = *(const float4*)&sp[4];
    }
    if (gr == 0) {
#pragma unroll
        for (int i = 0; i < 8; i++) s.Prow[0][gc + i] = v[i];
    }
    if (gq == 0) s.Fcol[0][gr] = v[0];
    __syncthreads();

    // RHS = A @ Sf via 8x4 tiles (threads 0..127) — overlapped with nothing; GJ follows
    if (tid < 128) {
        u64 acc[8][2];
        zero84(acc);
        mm84<LL, 68, LL, false>(acc, &s.sAT[it8], &s.sSf[jt4]);
        store84<68>(&s.sRHS[it8 * 68 + jt4], acc);
    }
    __syncthreads();

    // In-place GJ inversion of Sp (SPD, no pivoting), 1 sync per pivot.
    for (int p = 0; p < LL; p++) {
        int par = p & 1;
        float invd = __frcp_rn(s.Prow[par][p]);
        float fd = s.Fcol[par][gr] * invd;
        if (gr == p) {
#pragma unroll
            for (int i = 0; i < 8; i++) {
                int col = gc + i;
                v[i] = (col == p) ? invd : v[i] * invd;
            }
        } else {
            float4 q0 = *(float4*)&s.Prow[par][gc];
            float4 q1 = *(float4*)&s.Prow[par][gc + 4];
            float pr[8] = {q0.x, q0.y, q0.z, q0.w, q1.x, q1.y, q1.z, q1.w};
#pragma unroll
            for (int i = 0; i < 8; i++) {
                int col = gc + i;
                v[i] = (col == p) ? -fd : fmaf(-fd, pr[i], v[i]);
            }
        }
        int np = p + 1;
        if (np < LL) {
            if (gr == np) {
#pragma unroll
                for (int i = 0; i < 8; i++) s.Prow[par ^ 1][gc + i] = v[i];
            }
            if (np >= gc && np < gc + 8) s.Fcol[par ^ 1][gr] = v[np - gc];
        }
        __syncthreads();
    }

    // store Minv rows (symmetric -> usable directly as transposed operand)
    *(ulonglong2*)&s.sMI[gr * LL + gc] =
        make_ulonglong2(pk2(v[0], v[1]), pk2(v[2], v[3]));
    *(ulonglong2*)&s.sMI[gr * LL + gc + 4] =
        make_ulonglong2(pk2(v[4], v[5]), pk2(v[6], v[7]));
    __syncthreads();

    // X = Minv @ RHS (8x4 tiles, threads 0..127): write to g_J and sAT (A dead)
    if (tid < 128) {
        u64 acc[8][2];
        zero84(acc);
        mm84<LL, LL, 68, false>(acc, &s.sMI[it8], &s.sRHS[jt4]);
        store84<LL>(&g_J[gf * 4096 + it8 * LL + jt4], acc);
        store84<68>(&s.sAT[it8 * 68 + jt4], acc);
    }
    __syncthreads();

    // B_t = Sf - RHS^T @ X (8x4 tiles) ; b_t = mf - J mp1
    if (tid < 128) {
        u64 acc[8][2];
        load84<LL>(acc, &s.sSf[it8 * LL + jt4]);
        mm84<LL, 68, 68, true>(acc, &s.sRHS[it8], &s.sAT[jt4]);
        store84<LL>(&g_B[gf * 4096 + it8 * LL + jt4], acc);
    } else if (tid < 192) {
        int i = tid - 128;
        float a = s.smf[i];
        for (int m = 0; m < LL; m++) a = fmaf(-s.sAT[m * 68 + i], s.smp[m], a);
        g_bv[gf * LL + i] = a;
    }
}

// ---------------- backward RTS recursion with smem prefetch + lagged store ----------------
struct BwdS {
    float Sigs[LL * LL];    // carry: smoothed cov at t+1 (stride 64)
    float sX[2][LL * LL];   // X = J^T rows, double buffered
    float sB[LL * LL];      // B_t prefetch
    float T1T[LL * 68];     // (J@Sigs)^T
    float mus[LL];
    float musN[LL];
    float bv[2][LL];
};

__global__ __launch_bounds__(NT, 1) void bwd_kernel(float* __restrict__ outMu,
                                                    float* __restrict__ outSig) {
    BwdS& s = *(BwdS*)smem_raw;
    int tid = threadIdx.x;
    int b = blockIdx.x;
    int it8 = (tid >> 4) * 8;
    int jt4 = (tid & 15) * 4;

    {
        size_t gb = (size_t)(TT - 1) * BB + b;
        size_t g0 = (size_t)(TT - 2) * BB + b;
        for (int o = tid * 4; o < LL * LL; o += NT * 4) {
            float4 w = *(const float4*)&g_Sigf[gb * 4096 + o];
            *(float4*)&s.Sigs[o] = w;
            *(float4*)&outSig[gb * 4096 + o] = w;
            *(float4*)&s.sX[0][o] = *(const float4*)&g_J[g0 * 4096 + o];
        }
        if (tid < LL) {
            float w = g_muf[gb * LL + tid];
            s.mus[tid] = w;
            outMu[gb * LL + tid] = w;
            s.bv[0][tid] = g_bv[g0 * LL + tid];
        }
    }
    __syncthreads();

    for (int t = TT - 2; t >= 0; t--) {
        int cur = (TT - 2 - t) & 1;
        size_t gf = (size_t)t * BB + b;

        // m1: T1 = J @ Sigs (0..127) ; mu_s (128..191) ; prefetch B_t (192..447) ;
        //     lagged store of Sig_s(t+1) (448..511)
        if (tid < 128) {
            u64 acc[8][2];
            zero84(acc);
            mm84<LL, LL, LL, false>(acc, &s.sX[cur][it8], &s.Sigs[jt4]);
            storeT84<68>(&s.T1T[jt4 * 68 + it8], acc);
        } else if (tid < 192) {
            int i = tid - 128;
            float a = s.bv[cur][i];
            for (int k = 0; k < LL; k++) a = fmaf(s.sX[cur][k * LL + i], s.mus[k], a);
            s.musN[i] = a;
            outMu[gf * LL + i] = a;
        } else if (tid < 448) {
            for (int o = (tid - 192) * 4; o < LL * LL; o += 256 * 4)
                *(float4*)&s.sB[o] = *(const float4*)&g_B[gf * 4096 + o];
        } else if (t < TT - 2) {
            size_t gl = (size_t)(t + 1) * BB + b;
            for (int o = (tid - 448) * 4; o < LL * LL; o += 64 * 4)
                *(float4*)&outSig[gl * 4096 + o] = *(float4*)&s.Sigs[o];
        }
        __syncthreads();

        // m2: Sigs_new = B + T1 @ X (0..127, smem only) ; mus copy (128..191) ;
        //     prefetch J/bv t-1 (192..511)
        if (tid < 128) {
            u64 acc[8][2];
            load84<LL>(acc, &s.sB[it8 * LL + jt4]);
            mm84<LL, 68, LL, false>(acc, &s.T1T[it8], &s.sX[cur][jt4]);
            store84<LL>(&s.Sigs[it8 * LL + jt4], acc);
        } else if (tid < 192) {
            s.mus[tid - 128] = s.musN[tid - 128];
        } else if (t > 0) {
            size_t gn = (size_t)(t - 1) * BB + b;
            if (tid < 448) {
                for (int o = (tid - 192) * 4; o < LL * LL; o += 256 * 4)
                    *(float4*)&s.sX[cur ^ 1][o] = *(const float4*)&g_J[gn * 4096 + o];
            } else {
                s.bv[cur ^ 1][tid - 448] = g_bv[gn * LL + (tid - 448)];
            }
        }
        __syncthreads();
    }

    // epilogue: store Sig_s(0)
    for (int o = tid * 4; o < LL * LL; o += NT * 4)
        *(float4*)&outSig[(size_t)b * 4096 + o] = *(float4*)&s.Sigs[o];
}

// ---------------- launch ----------------
extern "C" void kernel_launch(void* const* d_in, const int* in_sizes, int n_in,
                              void* d_out, int out_size) {
    const float* obs   = (const float*)d_in[0];
    const float* start = (const float*)d_in[1];
    const float* W1    = (const float*)d_in[2];
    const float* b1    = (const float*)d_in[3];
    const float* W2    = (const float*)d_in[4];
    const float* b2    = (const float*)d_in[5];
    const float* A     = (const float*)d_in[6];
    const float* C     = (const float*)d_in[7];

    float* out = (float*)d_out;
    float* outMu  = out;                                   // (T,B,L)      409600
    float* outSig = out + 409600;                          // (T,B,L,L)  26214400
    float* outA   = out + 26624000;                        // (B,T,L,L)  26214400
    float* outC   = out + 52838400;                        // (B,T,D,L)  13107200

    cudaFuncSetAttribute(fwd_kernel, cudaFuncAttributeMaxDynamicSharedMemorySize, (int)sizeof(FwdS));
    cudaFuncSetAttribute(jk_kernel, cudaFuncAttributeMaxDynamicSharedMemorySize, (int)sizeof(JkS));
    cudaFuncSetAttribute(bwd_kernel, cudaFuncAttributeMaxDynamicSharedMemorySize, (int)sizeof(BwdS));

    w_kernel<<<BB * TT, 64>>>(obs, start, W1, b1, W2, b2);

    dim3 gA(4096 / 512, BB * TT / 32);
    mix_kernel<<<gA, 256>>>(A, outA, 4096);
    dim3 gC(2048 / 512, BB * TT / 32);
    mix_kernel<<<gC, 256>>>(C, outC, 2048);

    fwd_kernel<<<BB, NT, sizeof(FwdS)>>>(obs, outA, outC);

    dim3 gJ(BB, TT - 1);
    jk_kernel<<<gJ, NT, sizeof(JkS)>>>(outA);

    bwd_kernel<<<BB, NT, sizeof(BwdS)>>>(outMu, outSig);
}